// round 1
// baseline (speedup 1.0000x reference)
#include <cuda_runtime.h>

#define NN 50000
#define EE 800000
#define DD 64

// ---------------- scratch (device globals; no allocation allowed) ----------
__device__ float g_deg[NN];                 // deg, then dinv in place
__device__ int   g_cnt[NN];
__device__ int   g_rowptr[NN + 1];
__device__ int   g_cursor[NN];
__device__ int   g_csr_src[EE];
__device__ float g_csr_nrm[EE];

__device__ float g_TX1[NN * DD], g_TX2[NN * DD];
__device__ float g_TH1[NN * DD], g_TH2[NN * DD];
__device__ float g_HR [NN * DD], g_THR1[NN * DD], g_THR2[NN * DD];

__device__ float g_GA[3u * NN * DD];        // Zx, Rx, Hx
__device__ float g_GB[2u * NN * DD];        // Zh, Rh
__device__ float g_Z [NN * DD];
__device__ float g_Hh[NN * DD];

__device__ int   g_idx64;

// ---------------- setup kernels --------------------------------------------

// Detect whether edge_index is int64 (high 32-bit words all zero) or int32.
__global__ void k_detect(const unsigned int* __restrict__ p) {
    unsigned v = p[2 * threadIdx.x + 1];
    unsigned ball = __ballot_sync(0xffffffffu, v == 0u);
    if (threadIdx.x == 0) g_idx64 = (ball == 0xffffffffu) ? 1 : 0;
}

__global__ void k_zero() {
    int i = blockIdx.x * blockDim.x + threadIdx.x;
    if (i < NN) { g_deg[i] = 0.f; g_cnt[i] = 0; }
}

__device__ __forceinline__ void read_edge(const void* ei, int e, int& s, int& d) {
    if (g_idx64) {
        const long long* p = (const long long*)ei;
        s = (int)p[e]; d = (int)p[EE + e];
    } else {
        const int* p = (const int*)ei;
        s = p[e]; d = p[EE + e];
    }
}

__global__ void k_edge_deg(const void* __restrict__ ei, const float* __restrict__ ew) {
    int e = blockIdx.x * blockDim.x + threadIdx.x;
    if (e >= EE) return;
    int s, d; read_edge(ei, e, s, d);
    atomicAdd(&g_deg[s], ew[e]);
    atomicAdd(&g_cnt[d], 1);
}

__global__ void k_dinv() {
    int i = blockIdx.x * blockDim.x + threadIdx.x;
    if (i >= NN) return;
    float dg = g_deg[i];
    g_deg[i] = (dg > 0.f) ? rsqrtf(dg) : 0.f;
}

// single-block scan: exclusive prefix over g_cnt -> g_rowptr / g_cursor
__global__ void k_scan() {
    const int T = 1024;
    int t = threadIdx.x;
    const int CH = (NN + T - 1) / T;
    int beg = t * CH;
    int end = beg + CH; if (end > NN) end = NN; if (beg > NN) beg = NN;
    int s = 0;
    for (int i = beg; i < end; i++) s += g_cnt[i];
    __shared__ int sm[T];
    sm[t] = s; __syncthreads();
    for (int off = 1; off < T; off <<= 1) {
        int v = (t >= off) ? sm[t - off] : 0;
        __syncthreads();
        sm[t] += v;
        __syncthreads();
    }
    int run = sm[t] - s;   // exclusive prefix
    for (int i = beg; i < end; i++) {
        g_rowptr[i] = run; g_cursor[i] = run;
        run += g_cnt[i];
    }
    if (t == 0) g_rowptr[NN] = EE;
}

__global__ void k_fill(const void* __restrict__ ei, const float* __restrict__ ew) {
    int e = blockIdx.x * blockDim.x + threadIdx.x;
    if (e >= EE) return;
    int s, d; read_edge(ei, e, s, d);
    float nrm = ew[e] * g_deg[s] * g_deg[d];
    int pos = atomicAdd(&g_cursor[d], 1);
    g_csr_src[pos] = s;
    g_csr_nrm[pos] = nrm;
}

// ---------------- SpMM (gather, warp-per-row) ------------------------------
// out[row] = A*v[row] + B*(sum_e nrm*v[src_e]) + G*aux[row]

__device__ __forceinline__ void spmm_row(
    const float* __restrict__ v, const float* __restrict__ aux,
    float* __restrict__ out, int row, int lane, float A, float B, float G)
{
    int beg = g_rowptr[row], end = g_rowptr[row + 1];
    float acc0 = 0.f, acc1 = 0.f, acc2 = 0.f, acc3 = 0.f;
    int e = beg;
    for (; e + 1 < end; e += 2) {
        int   s0 = g_csr_src[e],     s1 = g_csr_src[e + 1];
        float w0 = g_csr_nrm[e],     w1 = g_csr_nrm[e + 1];
        const float* r0 = v + s0 * DD;
        const float* r1 = v + s1 * DD;
        acc0 += w0 * r0[lane];      acc1 += w0 * r0[lane + 32];
        acc2 += w1 * r1[lane];      acc3 += w1 * r1[lane + 32];
    }
    if (e < end) {
        int s0 = g_csr_src[e]; float w0 = g_csr_nrm[e];
        const float* r0 = v + s0 * DD;
        acc0 += w0 * r0[lane];      acc1 += w0 * r0[lane + 32];
    }
    acc0 += acc2; acc1 += acc3;
    int base = row * DD + lane;
    out[base]      = A * v[base]      + B * acc0 + G * aux[base];
    out[base + 32] = A * v[base + 32] + B * acc1 + G * aux[base + 32];
}

// pass 1 on X and H (grid.y = 2): T1 = (c-1)v - c*A v
__global__ void __launch_bounds__(256) k_spmm1_XH(
    const float* __restrict__ X, const float* __restrict__ H,
    const float* __restrict__ lam)
{
    int warp = threadIdx.x >> 5, lane = threadIdx.x & 31;
    int row = blockIdx.x * 8 + warp;
    if (row >= NN) return;
    float c = 2.f / __ldg(lam);
    const float* v = blockIdx.y ? H : X;
    float* out     = blockIdx.y ? g_TH1 : g_TX1;
    spmm_row(v, v, out, row, lane, c - 1.f, -c, 0.f);
}

// pass 2 on X and H: T2 = 2(c-1)T1 - 2c*A T1 - v0
__global__ void __launch_bounds__(256) k_spmm2_XH(
    const float* __restrict__ X, const float* __restrict__ H,
    const float* __restrict__ lam)
{
    int warp = threadIdx.x >> 5, lane = threadIdx.x & 31;
    int row = blockIdx.x * 8 + warp;
    if (row >= NN) return;
    float c = 2.f / __ldg(lam);
    const float* v   = blockIdx.y ? g_TH1 : g_TX1;
    const float* aux = blockIdx.y ? H : X;
    float* out       = blockIdx.y ? g_TH2 : g_TX2;
    spmm_row(v, aux, out, row, lane, 2.f * (c - 1.f), -2.f * c, -1.f);
}

__global__ void __launch_bounds__(256) k_spmm1_HR(const float* __restrict__ lam) {
    int warp = threadIdx.x >> 5, lane = threadIdx.x & 31;
    int row = blockIdx.x * 8 + warp;
    if (row >= NN) return;
    float c = 2.f / __ldg(lam);
    spmm_row(g_HR, g_HR, g_THR1, row, lane, c - 1.f, -c, 0.f);
}

__global__ void __launch_bounds__(256) k_spmm2_HR(const float* __restrict__ lam) {
    int warp = threadIdx.x >> 5, lane = threadIdx.x & 31;
    int row = blockIdx.x * 8 + warp;
    if (row >= NN) return;
    float c = 2.f / __ldg(lam);
    spmm_row(g_THR1, g_HR, g_THR2, row, lane, 2.f * (c - 1.f), -2.f * c, -1.f);
}

// ---------------- GEMM: C_g = sum_m A_m @ W[wsel(g)][m]  (K=192) ------------
// which=0: (X,TX1,TX2) -> g_GA with weights {0,2,4}
// which=1: (H,TH1,TH2) -> g_GB with weights {1,3}
// which=2: (HR,THR1,THR2) -> g_Hh with weight {5}

__global__ void __launch_bounds__(256) k_gemm(
    const float* __restrict__ Xin, const float* __restrict__ Hin,
    const float* __restrict__ W, int which)
{
    int g = blockIdx.y;
    const float *A0, *A1, *A2; float* C; int wsel;
    if (which == 0) { A0 = Xin;  A1 = g_TX1;  A2 = g_TX2;
                      C = g_GA + (size_t)g * NN * DD; wsel = (g == 0) ? 0 : (g == 1 ? 2 : 4); }
    else if (which == 1) { A0 = Hin;  A1 = g_TH1;  A2 = g_TH2;
                      C = g_GB + (size_t)g * NN * DD; wsel = (g == 0) ? 1 : 3; }
    else            { A0 = g_HR; A1 = g_THR1; A2 = g_THR2; C = g_Hh; wsel = 5; }

    const float* Abufs[3] = { A0, A1, A2 };
    int rowbase = blockIdx.x * 64;

    __shared__ float As[32][68];
    __shared__ float Bs[32][68];

    int tid = threadIdx.x;
    int tx = tid & 15, ty = tid >> 4;     // 16x16 -> each 4x4
    float acc[4][4];
    #pragma unroll
    for (int i = 0; i < 4; i++)
        #pragma unroll
        for (int j = 0; j < 4; j++) acc[i][j] = 0.f;

    for (int k0 = 0; k0 < 192; k0 += 32) {
        const float* Abuf = Abufs[k0 >> 6];
        int kofs = k0 & 63;
        #pragma unroll
        for (int i = 0; i < 8; i++) {
            int idx = tid + i * 256;
            int r = idx >> 5, kk = idx & 31;
            int grow = rowbase + r;
            As[kk][r] = (grow < NN) ? Abuf[grow * DD + kofs + kk] : 0.f;
        }
        const float* Bsrc = W + ((size_t)(wsel * 3 + (k0 >> 6)) * 64 + kofs) * 64;
        #pragma unroll
        for (int i = 0; i < 8; i++) {
            int idx = tid + i * 256;
            int kk = idx >> 6, c = idx & 63;
            Bs[kk][c] = Bsrc[kk * 64 + c];
        }
        __syncthreads();
        #pragma unroll
        for (int kk = 0; kk < 32; kk++) {
            float4 a4 = *(const float4*)&As[kk][ty * 4];
            float4 b4 = *(const float4*)&Bs[kk][tx * 4];
            float av[4] = { a4.x, a4.y, a4.z, a4.w };
            float bv[4] = { b4.x, b4.y, b4.z, b4.w };
            #pragma unroll
            for (int i = 0; i < 4; i++)
                #pragma unroll
                for (int j = 0; j < 4; j++) acc[i][j] += av[i] * bv[j];
        }
        __syncthreads();
    }
    #pragma unroll
    for (int i = 0; i < 4; i++) {
        int r = rowbase + ty * 4 + i;
        if (r < NN) {
            float4 o = make_float4(acc[i][0], acc[i][1], acc[i][2], acc[i][3]);
            *(float4*)&C[r * DD + tx * 4] = o;
        }
    }
}

// ---------------- elementwise ----------------------------------------------

__global__ void k_ew1(const float* __restrict__ H, const float* __restrict__ B) {
    int i = blockIdx.x * blockDim.x + threadIdx.x;
    if (i >= NN * DD) return;
    int d = i & (DD - 1);
    float Zl = g_GA[i] + g_GB[i] + B[d] + B[64 + d];
    float Rl = g_GA[(size_t)NN * DD + i] + g_GB[(size_t)NN * DD + i] + B[128 + d] + B[192 + d];
    float Z = 1.f / (1.f + __expf(-Zl));
    float R = 1.f / (1.f + __expf(-Rl));
    g_Z[i]  = Z;
    g_HR[i] = H[i] * R;
}

__global__ void k_ew2(const float* __restrict__ H, const float* __restrict__ B,
                      float* __restrict__ out) {
    int i = blockIdx.x * blockDim.x + threadIdx.x;
    if (i >= NN * DD) return;
    int d = i & (DD - 1);
    float Hl = g_GA[2u * NN * DD + i] + g_Hh[i] + B[256 + d] + B[320 + d];
    float Ht = tanhf(Hl);
    float Z = g_Z[i];
    out[i] = Z * Ht + (1.f - Z) * H[i];
}

// ---------------- launch ----------------------------------------------------

extern "C" void kernel_launch(void* const* d_in, const int* in_sizes, int n_in,
                              void* d_out, int out_size) {
    const float* X   = (const float*)d_in[0];
    const void*  EI  = d_in[1];
    const float* EW  = (const float*)d_in[2];
    const float* H   = (const float*)d_in[3];
    const float* LAM = (const float*)d_in[4];
    const float* W   = (const float*)d_in[5];
    const float* B   = (const float*)d_in[6];
    float* OUT = (float*)d_out;

    (void)in_sizes; (void)n_in; (void)out_size;

    // graph setup + CSR build
    k_detect<<<1, 32>>>((const unsigned int*)EI);
    k_zero<<<(NN + 255) / 256, 256>>>();
    k_edge_deg<<<(EE + 255) / 256, 256>>>(EI, EW);
    k_dinv<<<(NN + 255) / 256, 256>>>();
    k_scan<<<1, 1024>>>();
    k_fill<<<(EE + 255) / 256, 256>>>(EI, EW);

    // Chebyshev propagation for X and H
    dim3 sg((NN + 7) / 8, 2);
    k_spmm1_XH<<<sg, 256>>>(X, H, LAM);
    k_spmm2_XH<<<sg, 256>>>(X, H, LAM);

    // GEMMs: Zx/Rx/Hx and Zh/Rh
    dim3 ga((NN + 63) / 64, 3);
    dim3 gb((NN + 63) / 64, 2);
    k_gemm<<<ga, 256>>>(X, H, W, 0);
    k_gemm<<<gb, 256>>>(X, H, W, 1);

    // Z, R, HR
    k_ew1<<<(NN * DD + 255) / 256, 256>>>(H, B);

    // propagation for HR, then final GEMM
    dim3 sh((NN + 7) / 8, 1);
    k_spmm1_HR<<<sh, 256>>>(LAM);
    k_spmm2_HR<<<sh, 256>>>(LAM);
    dim3 gc((NN + 63) / 64, 1);
    k_gemm<<<gc, 256>>>(X, H, W, 2);

    // output gate
    k_ew2<<<(NN * DD + 255) / 256, 256>>>(H, B, OUT);
}

// round 3
// speedup vs baseline: 1.3644x; 1.3644x over previous
#include <cuda_runtime.h>
#include <cuda_bf16.h>
#include <cstdint>

#define NN 50000
#define EE 800000
#define DD 64
#define NND (NN * DD)

// ---------------- scratch (device globals; no allocation allowed) ----------
__device__ float g_deg[NN];
__device__ int   g_cnt[NN];
__device__ int   g_rowptr[NN + 1];
__device__ int   g_cursor[NN];
__device__ int   g_csr_src[EE];
__device__ float g_csr_nrm[EE];

__device__ float g_TX1[NND], g_TX2[NND];
__device__ float g_TH1[NND], g_TH2[NND];
__device__ float g_HR [NND], g_THR1[NND], g_THR2[NND];

__device__ float g_GA[3u * NND];        // Zx, Rx, Hx
__device__ float g_GB[2u * NND];        // Zh, Rh
__device__ float g_Z [NND];
__device__ float g_Hh[NND];

__device__ int   g_idx64;

// ---------------- setup kernels --------------------------------------------

__global__ void k_detect(const unsigned int* __restrict__ p) {
    unsigned v = p[2 * threadIdx.x + 1];
    unsigned ball = __ballot_sync(0xffffffffu, v == 0u);
    if (threadIdx.x == 0) g_idx64 = (ball == 0xffffffffu) ? 1 : 0;
}

__global__ void k_zero() {
    int i = blockIdx.x * blockDim.x + threadIdx.x;
    if (i < NN) { g_deg[i] = 0.f; g_cnt[i] = 0; }
}

__device__ __forceinline__ void read_edge(const void* ei, int e, int& s, int& d) {
    if (g_idx64) {
        const long long* p = (const long long*)ei;
        s = (int)p[e]; d = (int)p[EE + e];
    } else {
        const int* p = (const int*)ei;
        s = p[e]; d = p[EE + e];
    }
}

__global__ void k_edge_deg(const void* __restrict__ ei, const float* __restrict__ ew) {
    int e = blockIdx.x * blockDim.x + threadIdx.x;
    if (e >= EE) return;
    int s, d; read_edge(ei, e, s, d);
    atomicAdd(&g_deg[s], ew[e]);
    atomicAdd(&g_cnt[d], 1);
}

__global__ void k_dinv() {
    int i = blockIdx.x * blockDim.x + threadIdx.x;
    if (i >= NN) return;
    float dg = g_deg[i];
    g_deg[i] = (dg > 0.f) ? rsqrtf(dg) : 0.f;
}

__global__ void k_scan() {
    const int T = 1024;
    int t = threadIdx.x;
    const int CH = (NN + T - 1) / T;
    int beg = t * CH;
    int end = beg + CH; if (end > NN) end = NN; if (beg > NN) beg = NN;
    int s = 0;
    for (int i = beg; i < end; i++) s += g_cnt[i];
    __shared__ int sm[T];
    sm[t] = s; __syncthreads();
    for (int off = 1; off < T; off <<= 1) {
        int v = (t >= off) ? sm[t - off] : 0;
        __syncthreads();
        sm[t] += v;
        __syncthreads();
    }
    int run = sm[t] - s;
    for (int i = beg; i < end; i++) {
        g_rowptr[i] = run; g_cursor[i] = run;
        run += g_cnt[i];
    }
    if (t == 0) g_rowptr[NN] = EE;
}

__global__ void k_fill(const void* __restrict__ ei, const float* __restrict__ ew) {
    int e = blockIdx.x * blockDim.x + threadIdx.x;
    if (e >= EE) return;
    int s, d; read_edge(ei, e, s, d);
    float nrm = ew[e] * g_deg[s] * g_deg[d];
    int pos = atomicAdd(&g_cursor[d], 1);
    g_csr_src[pos] = s;
    g_csr_nrm[pos] = nrm;
}

// ---------------- SpMM (gather, warp-per-row) ------------------------------

__device__ __forceinline__ void spmm_row(
    const float* __restrict__ v, const float* __restrict__ aux,
    float* __restrict__ out, int row, int lane, float A, float B, float G)
{
    int beg = g_rowptr[row], end = g_rowptr[row + 1];
    float acc0 = 0.f, acc1 = 0.f, acc2 = 0.f, acc3 = 0.f;
    int e = beg;
    for (; e + 1 < end; e += 2) {
        int   s0 = g_csr_src[e],     s1 = g_csr_src[e + 1];
        float w0 = g_csr_nrm[e],     w1 = g_csr_nrm[e + 1];
        const float* r0 = v + s0 * DD;
        const float* r1 = v + s1 * DD;
        acc0 += w0 * r0[lane];      acc1 += w0 * r0[lane + 32];
        acc2 += w1 * r1[lane];      acc3 += w1 * r1[lane + 32];
    }
    if (e < end) {
        int s0 = g_csr_src[e]; float w0 = g_csr_nrm[e];
        const float* r0 = v + s0 * DD;
        acc0 += w0 * r0[lane];      acc1 += w0 * r0[lane + 32];
    }
    acc0 += acc2; acc1 += acc3;
    int base = row * DD + lane;
    out[base]      = A * v[base]      + B * acc0 + G * aux[base];
    out[base + 32] = A * v[base + 32] + B * acc1 + G * aux[base + 32];
}

__global__ void __launch_bounds__(256) k_spmm1_XH(
    const float* __restrict__ X, const float* __restrict__ H,
    const float* __restrict__ lam)
{
    int warp = threadIdx.x >> 5, lane = threadIdx.x & 31;
    int row = blockIdx.x * 8 + warp;
    if (row >= NN) return;
    float c = 2.f / __ldg(lam);
    const float* v = blockIdx.y ? H : X;
    float* out     = blockIdx.y ? g_TH1 : g_TX1;
    spmm_row(v, v, out, row, lane, c - 1.f, -c, 0.f);
}

__global__ void __launch_bounds__(256) k_spmm2_XH(
    const float* __restrict__ X, const float* __restrict__ H,
    const float* __restrict__ lam)
{
    int warp = threadIdx.x >> 5, lane = threadIdx.x & 31;
    int row = blockIdx.x * 8 + warp;
    if (row >= NN) return;
    float c = 2.f / __ldg(lam);
    const float* v   = blockIdx.y ? g_TH1 : g_TX1;
    const float* aux = blockIdx.y ? H : X;
    float* out       = blockIdx.y ? g_TH2 : g_TX2;
    spmm_row(v, aux, out, row, lane, 2.f * (c - 1.f), -2.f * c, -1.f);
}

__global__ void __launch_bounds__(256) k_spmm1_HR(const float* __restrict__ lam) {
    int warp = threadIdx.x >> 5, lane = threadIdx.x & 31;
    int row = blockIdx.x * 8 + warp;
    if (row >= NN) return;
    float c = 2.f / __ldg(lam);
    spmm_row(g_HR, g_HR, g_THR1, row, lane, c - 1.f, -c, 0.f);
}

__global__ void __launch_bounds__(256) k_spmm2_HR(const float* __restrict__ lam) {
    int warp = threadIdx.x >> 5, lane = threadIdx.x & 31;
    int row = blockIdx.x * 8 + warp;
    if (row >= NN) return;
    float c = 2.f / __ldg(lam);
    spmm_row(g_THR1, g_HR, g_THR2, row, lane, 2.f * (c - 1.f), -2.f * c, -1.f);
}

// ---------------- mma.sync bf16 GEMM ---------------------------------------
// D[128, 64] per gate = sum over 192-K of (A0|A1|A2)[128,64] @ W^T, bf16 3-way
// error-corrected split: Ah*Bh + Ah*Bl + Al*Bh (fp32 accumulate).

__device__ __forceinline__ void split2(float x, unsigned short& h, unsigned short& l) {
    __nv_bfloat16 hb = __float2bfloat16_rn(x);
    float r = x - __bfloat162float(hb);
    __nv_bfloat16 lb = __float2bfloat16_rn(r);
    h = *(unsigned short*)&hb;
    l = *(unsigned short*)&lb;
}

__device__ __forceinline__ void mma16816(float* c, uint32_t a0, uint32_t a1,
                                         uint32_t a2, uint32_t a3,
                                         uint32_t b0, uint32_t b1) {
    asm volatile(
        "mma.sync.aligned.m16n8k16.row.col.f32.bf16.bf16.f32 "
        "{%0,%1,%2,%3}, {%4,%5,%6,%7}, {%8,%9}, {%0,%1,%2,%3};"
        : "+f"(c[0]), "+f"(c[1]), "+f"(c[2]), "+f"(c[3])
        : "r"(a0), "r"(a1), "r"(a2), "r"(a3), "r"(b0), "r"(b1));
}

#define ASTR 200                 // padded K stride (elements): conflict-free frags
#define EL_AH 0
#define EL_AL 25600
#define EL_BH 51200
#define EL_BL 64000
#define DSM_BYTES (76800 * 2)    // 153600 B

__global__ void __launch_bounds__(256) k_gemm_mma(
    const float* __restrict__ Xin, const float* __restrict__ Hin,
    const float* __restrict__ W, int which)
{
    extern __shared__ unsigned short sm_el[];
    unsigned short* Ah = sm_el + EL_AH;
    unsigned short* Al = sm_el + EL_AL;
    unsigned short* Bh = sm_el + EL_BH;
    unsigned short* Bl = sm_el + EL_BL;

    int tid = threadIdx.x;
    int wid = tid >> 5, lane = tid & 31;
    int rowbase = blockIdx.x * 128;

    const float *A0, *A1, *A2; float* Cbase; int gates, wstart, wstep;
    if (which == 0)      { A0 = Xin;  A1 = g_TX1;  A2 = g_TX2;  Cbase = g_GA; gates = 3; wstart = 0; wstep = 2; }
    else if (which == 1) { A0 = Hin;  A1 = g_TH1;  A2 = g_TH2;  Cbase = g_GB; gates = 2; wstart = 1; wstep = 2; }
    else                 { A0 = g_HR; A1 = g_THR1; A2 = g_THR2; Cbase = g_Hh; gates = 1; wstart = 5; wstep = 0; }

    // ---- stage A: all 3 chunks (K=192), split into hi/lo bf16 ----
    for (int c = 0; c < 3; c++) {
        const float* Abuf = (c == 0) ? A0 : ((c == 1) ? A1 : A2);
        #pragma unroll
        for (int i = 0; i < 8; i++) {
            int lin = tid + i * 256;          // 2048 float4 units
            int m = lin >> 4;                 // row 0..127
            int kq = lin & 15;                // float4 along K-chunk
            int grow = rowbase + m;
            float4 v = make_float4(0.f, 0.f, 0.f, 0.f);
            if (grow < NN) v = *(const float4*)(Abuf + (size_t)grow * DD + kq * 4);
            unsigned short h0, l0, h1, l1, h2, l2, h3, l3;
            split2(v.x, h0, l0); split2(v.y, h1, l1);
            split2(v.z, h2, l2); split2(v.w, h3, l3);
            uint2 hp, lp;
            hp.x = (uint32_t)h0 | ((uint32_t)h1 << 16);
            hp.y = (uint32_t)h2 | ((uint32_t)h3 << 16);
            lp.x = (uint32_t)l0 | ((uint32_t)l1 << 16);
            lp.y = (uint32_t)l2 | ((uint32_t)l3 << 16);
            int eo = m * ASTR + c * 64 + kq * 4;
            *(uint2*)(Ah + eo) = hp;
            *(uint2*)(Al + eo) = lp;
        }
    }
    __syncthreads();

    // fragment base pointers (identical addressing for A and B tiles)
    int gq = lane >> 2, tg = lane & 3;
    int mrow = wid * 16;
    const uint32_t* pAh = (const uint32_t*)(Ah + (mrow + gq) * ASTR + tg * 2);
    const uint32_t* pAl = (const uint32_t*)(Al + (mrow + gq) * ASTR + tg * 2);
    const uint32_t* pBh0 = (const uint32_t*)(Bh + gq * ASTR + tg * 2);
    const uint32_t* pBl0 = (const uint32_t*)(Bl + gq * ASTR + tg * 2);

    for (int g = 0; g < gates; g++) {
        int wsel = wstart + g * wstep;
        // ---- stage B for this gate: W[wsel*3+c] transposed to [n][k] ----
        for (int c = 0; c < 3; c++) {
            const float* Wsrc = W + (size_t)(wsel * 3 + c) * 4096;
            #pragma unroll
            for (int i = 0; i < 4; i++) {
                int lin = tid + i * 256;      // 1024 units: (d, kq)
                int d  = lin & 63;
                int kq = lin >> 6;            // group of 4 k values
                unsigned short h[4], l[4];
                #pragma unroll
                for (int j = 0; j < 4; j++)
                    split2(Wsrc[(kq * 4 + j) * 64 + d], h[j], l[j]);
                uint2 hp, lp;
                hp.x = (uint32_t)h[0] | ((uint32_t)h[1] << 16);
                hp.y = (uint32_t)h[2] | ((uint32_t)h[3] << 16);
                lp.x = (uint32_t)l[0] | ((uint32_t)l[1] << 16);
                lp.y = (uint32_t)l[2] | ((uint32_t)l[3] << 16);
                int eo = d * ASTR + c * 64 + kq * 4;
                *(uint2*)(Bh + eo) = hp;
                *(uint2*)(Bl + eo) = lp;
            }
        }
        __syncthreads();

        float acc[32];
        #pragma unroll
        for (int i = 0; i < 32; i++) acc[i] = 0.f;

        #pragma unroll 2
        for (int ks = 0; ks < 12; ks++) {
            int kw = ks * 8;  // word offset along K
            uint32_t ah0 = pAh[kw], ah1 = pAh[kw + 800];
            uint32_t ah2 = pAh[kw + 4], ah3 = pAh[kw + 804];
            uint32_t al0 = pAl[kw], al1 = pAl[kw + 800];
            uint32_t al2 = pAl[kw + 4], al3 = pAl[kw + 804];
            #pragma unroll
            for (int nt = 0; nt < 8; nt++) {
                int bo = nt * 800 + kw;
                uint32_t bh0 = pBh0[bo], bh1 = pBh0[bo + 4];
                uint32_t bl0 = pBl0[bo], bl1 = pBl0[bo + 4];
                float* a = acc + nt * 4;
                mma16816(a, ah0, ah1, ah2, ah3, bh0, bh1);
                mma16816(a, ah0, ah1, ah2, ah3, bl0, bl1);
                mma16816(a, al0, al1, al2, al3, bh0, bh1);
            }
        }

        // ---- epilogue ----
        float* C = Cbase + (size_t)g * NND;
        int r0 = rowbase + mrow + gq;
        int r1 = r0 + 8;
        #pragma unroll
        for (int nt = 0; nt < 8; nt++) {
            int col = nt * 8 + tg * 2;
            if (r0 < NN) *(float2*)(C + (size_t)r0 * DD + col) = make_float2(acc[nt*4+0], acc[nt*4+1]);
            if (r1 < NN) *(float2*)(C + (size_t)r1 * DD + col) = make_float2(acc[nt*4+2], acc[nt*4+3]);
        }
        __syncthreads();
    }
}

// ---------------- elementwise ----------------------------------------------

__global__ void k_ew1(const float* __restrict__ H, const float* __restrict__ B) {
    int i = blockIdx.x * blockDim.x + threadIdx.x;
    if (i >= NND) return;
    int d = i & (DD - 1);
    float Zl = g_GA[i] + g_GB[i] + B[d] + B[64 + d];
    float Rl = g_GA[(size_t)NND + i] + g_GB[(size_t)NND + i] + B[128 + d] + B[192 + d];
    float Z = 1.f / (1.f + __expf(-Zl));
    float R = 1.f / (1.f + __expf(-Rl));
    g_Z[i]  = Z;
    g_HR[i] = H[i] * R;
}

__global__ void k_ew2(const float* __restrict__ H, const float* __restrict__ B,
                      float* __restrict__ out) {
    int i = blockIdx.x * blockDim.x + threadIdx.x;
    if (i >= NND) return;
    int d = i & (DD - 1);
    float Hl = g_GA[2u * NND + i] + g_Hh[i] + B[256 + d] + B[320 + d];
    float Ht = tanhf(Hl);
    float Z = g_Z[i];
    out[i] = Z * Ht + (1.f - Z) * H[i];
}

// ---------------- launch ----------------------------------------------------

extern "C" void kernel_launch(void* const* d_in, const int* in_sizes, int n_in,
                              void* d_out, int out_size) {
    const float* X   = (const float*)d_in[0];
    const void*  EI  = d_in[1];
    const float* EW  = (const float*)d_in[2];
    const float* H   = (const float*)d_in[3];
    const float* LAM = (const float*)d_in[4];
    const float* W   = (const float*)d_in[5];
    const float* B   = (const float*)d_in[6];
    float* OUT = (float*)d_out;

    (void)in_sizes; (void)n_in; (void)out_size;

    static int smem_set = 0;
    if (!smem_set) {
        cudaFuncSetAttribute(k_gemm_mma, cudaFuncAttributeMaxDynamicSharedMemorySize, DSM_BYTES);
        smem_set = 1;
    }

    // graph setup + CSR build
    k_detect<<<1, 32>>>((const unsigned int*)EI);
    k_zero<<<(NN + 255) / 256, 256>>>();
    k_edge_deg<<<(EE + 255) / 256, 256>>>(EI, EW);
    k_dinv<<<(NN + 255) / 256, 256>>>();
    k_scan<<<1, 1024>>>();
    k_fill<<<(EE + 255) / 256, 256>>>(EI, EW);

    // Chebyshev propagation for X and H
    dim3 sg((NN + 7) / 8, 2);
    k_spmm1_XH<<<sg, 256>>>(X, H, LAM);
    k_spmm2_XH<<<sg, 256>>>(X, H, LAM);

    // tensor-core GEMMs
    int ntiles = (NN + 127) / 128;
    k_gemm_mma<<<ntiles, 256, DSM_BYTES>>>(X, H, W, 0);
    k_gemm_mma<<<ntiles, 256, DSM_BYTES>>>(X, H, W, 1);

    // Z, R, HR
    k_ew1<<<(NND + 255) / 256, 256>>>(H, B);

    // propagation for HR, then final GEMM
    dim3 sh((NN + 7) / 8, 1);
    k_spmm1_HR<<<sh, 256>>>(LAM);
    k_spmm2_HR<<<sh, 256>>>(LAM);
    k_gemm_mma<<<ntiles, 256, DSM_BYTES>>>(X, H, W, 2);

    // output gate
    k_ew2<<<(NND + 255) / 256, 256>>>(H, B, OUT);
}

// round 4
// speedup vs baseline: 1.4754x; 1.0813x over previous
#include <cuda_runtime.h>
#include <cuda_bf16.h>
#include <cstdint>

#define NN 50000
#define EE 800000
#define DD 64
#define NND (NN * DD)

// ---------------- scratch (device globals; no allocation allowed) ----------
__device__ float g_deg[NN];
__device__ int   g_cnt[NN];
__device__ int   g_rowptr[NN + 1];
__device__ int   g_cursor[NN];
__device__ int   g_csr_src[EE];
__device__ float g_csr_nrm[EE];

__device__ float g_TX1[NND], g_TX2[NND];
__device__ float g_TH1[NND], g_TH2[NND];
__device__ float g_HR [NND], g_THR1[NND], g_THR2[NND];

__device__ float g_GA[3u * NND];        // Zx, Rx, Hx
__device__ float g_GB[2u * NND];        // Zh, Rh
__device__ float g_Z [NND];
__device__ float g_Hh[NND];

// pre-split weights, transposed to [mat][dout][kin], bf16 hi/lo
__device__ unsigned short g_Wh[18 * 4096];
__device__ unsigned short g_Wl[18 * 4096];

__device__ int   g_idx64;

// ---------------- setup kernels --------------------------------------------

__global__ void k_detect(const unsigned int* __restrict__ p) {
    unsigned v = p[2 * threadIdx.x + 1];
    unsigned ball = __ballot_sync(0xffffffffu, v == 0u);
    if (threadIdx.x == 0) g_idx64 = (ball == 0xffffffffu) ? 1 : 0;
}

__global__ void k_zero() {
    int i = blockIdx.x * blockDim.x + threadIdx.x;
    if (i < NN) { g_deg[i] = 0.f; g_cnt[i] = 0; }
}

__device__ __forceinline__ void split2(float x, unsigned short& h, unsigned short& l) {
    __nv_bfloat16 hb = __float2bfloat16_rn(x);
    float r = x - __bfloat162float(hb);
    __nv_bfloat16 lb = __float2bfloat16_rn(r);
    h = *(unsigned short*)&hb;
    l = *(unsigned short*)&lb;
}

// transpose + split weights: W[mat][kin][dout] -> g_Wh/Wl[mat][dout][kin]
__global__ void k_wsplit(const float* __restrict__ W) {
    int e = blockIdx.x * blockDim.x + threadIdx.x;
    if (e >= 18 * 4096) return;
    int mat = e >> 12;
    int kin = (e >> 6) & 63;
    int dout = e & 63;
    unsigned short h, l;
    split2(W[e], h, l);
    int o = (mat << 12) | (dout << 6) | kin;
    g_Wh[o] = h;
    g_Wl[o] = l;
}

__device__ __forceinline__ void read_edge(const void* ei, int e, int& s, int& d) {
    if (g_idx64) {
        const long long* p = (const long long*)ei;
        s = (int)p[e]; d = (int)p[EE + e];
    } else {
        const int* p = (const int*)ei;
        s = p[e]; d = p[EE + e];
    }
}

__global__ void k_edge_deg(const void* __restrict__ ei, const float* __restrict__ ew) {
    int e = blockIdx.x * blockDim.x + threadIdx.x;
    if (e >= EE) return;
    int s, d; read_edge(ei, e, s, d);
    atomicAdd(&g_deg[s], ew[e]);
    atomicAdd(&g_cnt[d], 1);
}

__global__ void k_dinv() {
    int i = blockIdx.x * blockDim.x + threadIdx.x;
    if (i >= NN) return;
    float dg = g_deg[i];
    g_deg[i] = (dg > 0.f) ? rsqrtf(dg) : 0.f;
}

__global__ void k_scan() {
    const int T = 1024;
    int t = threadIdx.x;
    const int CH = (NN + T - 1) / T;
    int beg = t * CH;
    int end = beg + CH; if (end > NN) end = NN; if (beg > NN) beg = NN;
    int s = 0;
    for (int i = beg; i < end; i++) s += g_cnt[i];
    __shared__ int sm[T];
    sm[t] = s; __syncthreads();
    for (int off = 1; off < T; off <<= 1) {
        int v = (t >= off) ? sm[t - off] : 0;
        __syncthreads();
        sm[t] += v;
        __syncthreads();
    }
    int run = sm[t] - s;
    for (int i = beg; i < end; i++) {
        g_rowptr[i] = run; g_cursor[i] = run;
        run += g_cnt[i];
    }
    if (t == 0) g_rowptr[NN] = EE;
}

__global__ void k_fill(const void* __restrict__ ei, const float* __restrict__ ew) {
    int e = blockIdx.x * blockDim.x + threadIdx.x;
    if (e >= EE) return;
    int s, d; read_edge(ei, e, s, d);
    float nrm = ew[e] * g_deg[s] * g_deg[d];
    int pos = atomicAdd(&g_cursor[d], 1);
    g_csr_src[pos] = s;
    g_csr_nrm[pos] = nrm;
}

// ---------------- SpMM (gather, warp-per-row, float2 lanes) ----------------
// out[row] = A*v[row] + B*(sum_e nrm*v[src_e]) + G*aux[row]

__device__ __forceinline__ void spmm_row(
    const float* __restrict__ v, const float* __restrict__ aux,
    float* __restrict__ out, int row, int lane, float A, float B, float G)
{
    int beg = g_rowptr[row], end = g_rowptr[row + 1];
    float acc0 = 0.f, acc1 = 0.f, acc2 = 0.f, acc3 = 0.f;
    int e = beg;
    for (; e + 1 < end; e += 2) {
        int   s0 = g_csr_src[e],     s1 = g_csr_src[e + 1];
        float w0 = g_csr_nrm[e],     w1 = g_csr_nrm[e + 1];
        float2 r0 = *(const float2*)(v + s0 * DD + lane * 2);
        float2 r1 = *(const float2*)(v + s1 * DD + lane * 2);
        acc0 += w0 * r0.x;  acc1 += w0 * r0.y;
        acc2 += w1 * r1.x;  acc3 += w1 * r1.y;
    }
    if (e < end) {
        int s0 = g_csr_src[e]; float w0 = g_csr_nrm[e];
        float2 r0 = *(const float2*)(v + s0 * DD + lane * 2);
        acc0 += w0 * r0.x;  acc1 += w0 * r0.y;
    }
    acc0 += acc2; acc1 += acc3;
    int base = row * DD + lane * 2;
    float2 vc = *(const float2*)(v + base);
    float2 ax = *(const float2*)(aux + base);
    float2 o;
    o.x = A * vc.x + B * acc0 + G * ax.x;
    o.y = A * vc.y + B * acc1 + G * ax.y;
    *(float2*)(out + base) = o;
}

__global__ void __launch_bounds__(256) k_spmm1_XH(
    const float* __restrict__ X, const float* __restrict__ H,
    const float* __restrict__ lam)
{
    int warp = threadIdx.x >> 5, lane = threadIdx.x & 31;
    int row = blockIdx.x * 8 + warp;
    if (row >= NN) return;
    float c = 2.f / __ldg(lam);
    const float* v = blockIdx.y ? H : X;
    float* out     = blockIdx.y ? g_TH1 : g_TX1;
    spmm_row(v, v, out, row, lane, c - 1.f, -c, 0.f);
}

__global__ void __launch_bounds__(256) k_spmm2_XH(
    const float* __restrict__ X, const float* __restrict__ H,
    const float* __restrict__ lam)
{
    int warp = threadIdx.x >> 5, lane = threadIdx.x & 31;
    int row = blockIdx.x * 8 + warp;
    if (row >= NN) return;
    float c = 2.f / __ldg(lam);
    const float* v   = blockIdx.y ? g_TH1 : g_TX1;
    const float* aux = blockIdx.y ? H : X;
    float* out       = blockIdx.y ? g_TH2 : g_TX2;
    spmm_row(v, aux, out, row, lane, 2.f * (c - 1.f), -2.f * c, -1.f);
}

__global__ void __launch_bounds__(256) k_spmm1_HR(const float* __restrict__ lam) {
    int warp = threadIdx.x >> 5, lane = threadIdx.x & 31;
    int row = blockIdx.x * 8 + warp;
    if (row >= NN) return;
    float c = 2.f / __ldg(lam);
    spmm_row(g_HR, g_HR, g_THR1, row, lane, c - 1.f, -c, 0.f);
}

__global__ void __launch_bounds__(256) k_spmm2_HR(const float* __restrict__ lam) {
    int warp = threadIdx.x >> 5, lane = threadIdx.x & 31;
    int row = blockIdx.x * 8 + warp;
    if (row >= NN) return;
    float c = 2.f / __ldg(lam);
    spmm_row(g_THR1, g_HR, g_THR2, row, lane, 2.f * (c - 1.f), -2.f * c, -1.f);
}

// ---------------- mma.sync bf16 GEMM ---------------------------------------
// D[128, 64] per gate = sum over 192-K of (A0|A1|A2)[128,64] @ W^T, bf16 3-way
// error-corrected split: Ah*Bh + Ah*Bl + Al*Bh (fp32 accumulate).

__device__ __forceinline__ void mma16816(float* c, uint32_t a0, uint32_t a1,
                                         uint32_t a2, uint32_t a3,
                                         uint32_t b0, uint32_t b1) {
    asm volatile(
        "mma.sync.aligned.m16n8k16.row.col.f32.bf16.bf16.f32 "
        "{%0,%1,%2,%3}, {%4,%5,%6,%7}, {%8,%9}, {%0,%1,%2,%3};"
        : "+f"(c[0]), "+f"(c[1]), "+f"(c[2]), "+f"(c[3])
        : "r"(a0), "r"(a1), "r"(a2), "r"(a3), "r"(b0), "r"(b1));
}

#define ASTR 200                 // padded K stride (elements)
#define EL_AH 0
#define EL_AL 25600
#define EL_BH 51200
#define EL_BL 64000
#define DSM_BYTES (76800 * 2)    // 153600 B

// whichsel: 0 -> blockIdx.y picks which 0/1 ; 2 -> final HR gemm
__global__ void __launch_bounds__(256) k_gemm_mma(
    const float* __restrict__ Xin, const float* __restrict__ Hin, int whichsel)
{
    extern __shared__ unsigned short sm_el[];
    unsigned short* Ah = sm_el + EL_AH;
    unsigned short* Al = sm_el + EL_AL;
    unsigned short* Bh = sm_el + EL_BH;
    unsigned short* Bl = sm_el + EL_BL;

    int tid = threadIdx.x;
    int wid = tid >> 5, lane = tid & 31;
    int rowbase = blockIdx.x * 128;
    int which = (whichsel == 2) ? 2 : (int)blockIdx.y;

    const float *A0, *A1, *A2; float* Cbase; int gates, wstart, wstep;
    if (which == 0)      { A0 = Xin;  A1 = g_TX1;  A2 = g_TX2;  Cbase = g_GA; gates = 3; wstart = 0; wstep = 2; }
    else if (which == 1) { A0 = Hin;  A1 = g_TH1;  A2 = g_TH2;  Cbase = g_GB; gates = 2; wstart = 1; wstep = 2; }
    else                 { A0 = g_HR; A1 = g_THR1; A2 = g_THR2; Cbase = g_Hh; gates = 1; wstart = 5; wstep = 0; }

    // ---- stage A: 3 chunks (K=192), split into hi/lo bf16 ----
    for (int c = 0; c < 3; c++) {
        const float* Abuf = (c == 0) ? A0 : ((c == 1) ? A1 : A2);
        #pragma unroll
        for (int i = 0; i < 8; i++) {
            int lin = tid + i * 256;          // 2048 float4 units
            int m = lin >> 4;
            int kq = lin & 15;
            int grow = rowbase + m;
            float4 v = make_float4(0.f, 0.f, 0.f, 0.f);
            if (grow < NN) v = *(const float4*)(Abuf + (size_t)grow * DD + kq * 4);
            unsigned short h0, l0, h1, l1, h2, l2, h3, l3;
            split2(v.x, h0, l0); split2(v.y, h1, l1);
            split2(v.z, h2, l2); split2(v.w, h3, l3);
            uint2 hp, lp;
            hp.x = (uint32_t)h0 | ((uint32_t)h1 << 16);
            hp.y = (uint32_t)h2 | ((uint32_t)h3 << 16);
            lp.x = (uint32_t)l0 | ((uint32_t)l1 << 16);
            lp.y = (uint32_t)l2 | ((uint32_t)l3 << 16);
            int eo = m * ASTR + c * 64 + kq * 4;
            *(uint2*)(Ah + eo) = hp;
            *(uint2*)(Al + eo) = lp;
        }
    }
    __syncthreads();

    // fragment base pointers
    int gq = lane >> 2, tg = lane & 3;
    int mrow = wid * 16;
    const uint32_t* pAh = (const uint32_t*)(Ah + (mrow + gq) * ASTR + tg * 2);
    const uint32_t* pAl = (const uint32_t*)(Al + (mrow + gq) * ASTR + tg * 2);
    const uint32_t* pBh0 = (const uint32_t*)(Bh + gq * ASTR + tg * 2);
    const uint32_t* pBl0 = (const uint32_t*)(Bl + gq * ASTR + tg * 2);

    for (int g = 0; g < gates; g++) {
        int wsel = wstart + g * wstep;
        // ---- stage B: copy pre-split transposed weights (uint4) ----
        #pragma unroll
        for (int c = 0; c < 3; c++) {
            int mat = wsel * 3 + c;
            const uint4* srcH = (const uint4*)(g_Wh + (mat << 12));
            const uint4* srcL = (const uint4*)(g_Wl + (mat << 12));
            #pragma unroll
            for (int i = 0; i < 2; i++) {
                int lin = tid + i * 256;      // 512 uint4 units: (d, k8)
                int d  = lin >> 3;
                int k8 = (lin & 7) * 8;
                int eo = d * ASTR + c * 64 + k8;
                *(uint4*)(Bh + eo) = srcH[lin];
                *(uint4*)(Bl + eo) = srcL[lin];
            }
        }
        __syncthreads();

        float acc[32];
        #pragma unroll
        for (int i = 0; i < 32; i++) acc[i] = 0.f;

        #pragma unroll 2
        for (int ks = 0; ks < 12; ks++) {
            int kw = ks * 8;
            uint32_t ah0 = pAh[kw], ah1 = pAh[kw + 800];
            uint32_t ah2 = pAh[kw + 4], ah3 = pAh[kw + 804];
            uint32_t al0 = pAl[kw], al1 = pAl[kw + 800];
            uint32_t al2 = pAl[kw + 4], al3 = pAl[kw + 804];
            #pragma unroll
            for (int nt = 0; nt < 8; nt++) {
                int bo = nt * 800 + kw;
                uint32_t bh0 = pBh0[bo], bh1 = pBh0[bo + 4];
                uint32_t bl0 = pBl0[bo], bl1 = pBl0[bo + 4];
                float* a = acc + nt * 4;
                mma16816(a, ah0, ah1, ah2, ah3, bh0, bh1);
                mma16816(a, ah0, ah1, ah2, ah3, bl0, bl1);
                mma16816(a, al0, al1, al2, al3, bh0, bh1);
            }
        }

        // ---- epilogue ----
        float* C = Cbase + (size_t)g * NND;
        int r0 = rowbase + mrow + gq;
        int r1 = r0 + 8;
        #pragma unroll
        for (int nt = 0; nt < 8; nt++) {
            int col = nt * 8 + tg * 2;
            if (r0 < NN) *(float2*)(C + (size_t)r0 * DD + col) = make_float2(acc[nt*4+0], acc[nt*4+1]);
            if (r1 < NN) *(float2*)(C + (size_t)r1 * DD + col) = make_float2(acc[nt*4+2], acc[nt*4+3]);
        }
        __syncthreads();
    }
}

// ---------------- elementwise (float4) --------------------------------------

__global__ void k_ew1(const float* __restrict__ H, const float* __restrict__ B) {
    int i4 = blockIdx.x * blockDim.x + threadIdx.x;
    if (i4 >= NND / 4) return;
    int i = i4 * 4;
    int d = i & (DD - 1);
    float4 ga0 = *(const float4*)(g_GA + i);
    float4 gb0 = *(const float4*)(g_GB + i);
    float4 ga1 = *(const float4*)(g_GA + (size_t)NND + i);
    float4 gb1 = *(const float4*)(g_GB + (size_t)NND + i);
    float4 b0  = *(const float4*)(B + d);
    float4 b1  = *(const float4*)(B + 64 + d);
    float4 b2  = *(const float4*)(B + 128 + d);
    float4 b3  = *(const float4*)(B + 192 + d);
    float4 h   = *(const float4*)(H + i);
    float4 z, hr;
    {
        float zl = ga0.x + gb0.x + b0.x + b1.x;
        float rl = ga1.x + gb1.x + b2.x + b3.x;
        z.x = 1.f / (1.f + __expf(-zl));
        hr.x = h.x / (1.f + __expf(-rl));
    }
    {
        float zl = ga0.y + gb0.y + b0.y + b1.y;
        float rl = ga1.y + gb1.y + b2.y + b3.y;
        z.y = 1.f / (1.f + __expf(-zl));
        hr.y = h.y / (1.f + __expf(-rl));
    }
    {
        float zl = ga0.z + gb0.z + b0.z + b1.z;
        float rl = ga1.z + gb1.z + b2.z + b3.z;
        z.z = 1.f / (1.f + __expf(-zl));
        hr.z = h.z / (1.f + __expf(-rl));
    }
    {
        float zl = ga0.w + gb0.w + b0.w + b1.w;
        float rl = ga1.w + gb1.w + b2.w + b3.w;
        z.w = 1.f / (1.f + __expf(-zl));
        hr.w = h.w / (1.f + __expf(-rl));
    }
    *(float4*)(g_Z + i)  = z;
    *(float4*)(g_HR + i) = hr;
}

__global__ void k_ew2(const float* __restrict__ H, const float* __restrict__ B,
                      float* __restrict__ out) {
    int i4 = blockIdx.x * blockDim.x + threadIdx.x;
    if (i4 >= NND / 4) return;
    int i = i4 * 4;
    int d = i & (DD - 1);
    float4 gx = *(const float4*)(g_GA + 2u * NND + i);
    float4 gh = *(const float4*)(g_Hh + i);
    float4 b0 = *(const float4*)(B + 256 + d);
    float4 b1 = *(const float4*)(B + 320 + d);
    float4 z  = *(const float4*)(g_Z + i);
    float4 h  = *(const float4*)(H + i);
    float4 o;
    o.x = z.x * tanhf(gx.x + gh.x + b0.x + b1.x) + (1.f - z.x) * h.x;
    o.y = z.y * tanhf(gx.y + gh.y + b0.y + b1.y) + (1.f - z.y) * h.y;
    o.z = z.z * tanhf(gx.z + gh.z + b0.z + b1.z) + (1.f - z.z) * h.z;
    o.w = z.w * tanhf(gx.w + gh.w + b0.w + b1.w) + (1.f - z.w) * h.w;
    *(float4*)(out + i) = o;
}

// ---------------- launch ----------------------------------------------------

extern "C" void kernel_launch(void* const* d_in, const int* in_sizes, int n_in,
                              void* d_out, int out_size) {
    const float* X   = (const float*)d_in[0];
    const void*  EI  = d_in[1];
    const float* EW  = (const float*)d_in[2];
    const float* H   = (const float*)d_in[3];
    const float* LAM = (const float*)d_in[4];
    const float* W   = (const float*)d_in[5];
    const float* B   = (const float*)d_in[6];
    float* OUT = (float*)d_out;

    (void)in_sizes; (void)n_in; (void)out_size;

    cudaFuncSetAttribute(k_gemm_mma, cudaFuncAttributeMaxDynamicSharedMemorySize, DSM_BYTES);

    // weight pre-split + graph setup + CSR build
    k_detect<<<1, 32>>>((const unsigned int*)EI);
    k_wsplit<<<(18 * 4096 + 255) / 256, 256>>>(W);
    k_zero<<<(NN + 255) / 256, 256>>>();
    k_edge_deg<<<(EE + 255) / 256, 256>>>(EI, EW);
    k_dinv<<<(NN + 255) / 256, 256>>>();
    k_scan<<<1, 1024>>>();
    k_fill<<<(EE + 255) / 256, 256>>>(EI, EW);

    // Chebyshev propagation for X and H
    dim3 sg((NN + 7) / 8, 2);
    k_spmm1_XH<<<sg, 256>>>(X, H, LAM);
    k_spmm2_XH<<<sg, 256>>>(X, H, LAM);

    // merged tensor-core GEMMs for X-gates and H-gates
    int ntiles = (NN + 127) / 128;
    k_gemm_mma<<<dim3(ntiles, 2), 256, DSM_BYTES>>>(X, H, 0);

    // Z, R, HR
    k_ew1<<<(NND / 4 + 255) / 256, 256>>>(H, B);

    // propagation for HR, then final GEMM
    dim3 sh((NN + 7) / 8, 1);
    k_spmm1_HR<<<sh, 256>>>(LAM);
    k_spmm2_HR<<<sh, 256>>>(LAM);
    k_gemm_mma<<<dim3(ntiles, 1), 256, DSM_BYTES>>>(X, H, 2);

    // output gate
    k_ew2<<<(NND / 4 + 255) / 256, 256>>>(H, B, OUT);
}

// round 5
// speedup vs baseline: 1.5240x; 1.0330x over previous
#include <cuda_runtime.h>
#include <cuda_bf16.h>
#include <cuda_fp16.h>
#include <cstdint>

#define NN 50000
#define EE 800000
#define DD 64
#define NND (NN * DD)

// ---------------- scratch (device globals; no allocation allowed) ----------
__device__ float g_deg[NN];
__device__ int   g_cnt[NN];
__device__ int   g_rowptr[NN + 1];
__device__ int   g_cursor[NN];
__device__ int   g_csr_src[EE];
__device__ float g_csr_nrm[EE];

__device__ float g_TX1[NND], g_TX2[NND];
__device__ float g_TH1[NND], g_TH2[NND];
__device__ float g_HR [NND], g_THR1[NND], g_THR2[NND];

// fp16 gather tables (packed half2, 32 per row)
__device__ __half2 g_X16 [NND / 2], g_H16 [NND / 2];
__device__ __half2 g_TX1h[NND / 2], g_TH1h[NND / 2];
__device__ __half2 g_HRh [NND / 2], g_THR1h[NND / 2];

__device__ float g_GA[3u * NND];        // Zx, Rx, Hx
__device__ float g_GB[2u * NND];        // Zh, Rh
__device__ float g_Z [NND];
__device__ float g_Hh[NND];

// pre-split weights, transposed to [mat][dout][kin], bf16 hi/lo
__device__ unsigned short g_Wh[18 * 4096];
__device__ unsigned short g_Wl[18 * 4096];

__device__ int   g_idx64;

// ---------------- setup kernels --------------------------------------------

__global__ void k_detect(const unsigned int* __restrict__ p) {
    unsigned v = p[2 * threadIdx.x + 1];
    unsigned ball = __ballot_sync(0xffffffffu, v == 0u);
    if (threadIdx.x == 0) g_idx64 = (ball == 0xffffffffu) ? 1 : 0;
}

__global__ void k_tohalf(const float* __restrict__ X, const float* __restrict__ H) {
    int i = blockIdx.x * blockDim.x + threadIdx.x;
    if (i >= NND / 2) return;
    float2 x = ((const float2*)X)[i];
    float2 h = ((const float2*)H)[i];
    g_X16[i] = __floats2half2_rn(x.x, x.y);
    g_H16[i] = __floats2half2_rn(h.x, h.y);
}

__global__ void k_zero() {
    int i = blockIdx.x * blockDim.x + threadIdx.x;
    if (i < NN) { g_deg[i] = 0.f; g_cnt[i] = 0; }
}

__device__ __forceinline__ void split2(float x, unsigned short& h, unsigned short& l) {
    __nv_bfloat16 hb = __float2bfloat16_rn(x);
    float r = x - __bfloat162float(hb);
    __nv_bfloat16 lb = __float2bfloat16_rn(r);
    h = *(unsigned short*)&hb;
    l = *(unsigned short*)&lb;
}

// transpose + split weights: W[mat][kin][dout] -> g_Wh/Wl[mat][dout][kin]
__global__ void k_wsplit(const float* __restrict__ W) {
    int e = blockIdx.x * blockDim.x + threadIdx.x;
    if (e >= 18 * 4096) return;
    int mat = e >> 12;
    int kin = (e >> 6) & 63;
    int dout = e & 63;
    unsigned short h, l;
    split2(W[e], h, l);
    int o = (mat << 12) | (dout << 6) | kin;
    g_Wh[o] = h;
    g_Wl[o] = l;
}

__device__ __forceinline__ void read_edge(const void* ei, int e, int& s, int& d) {
    if (g_idx64) {
        const long long* p = (const long long*)ei;
        s = (int)p[e]; d = (int)p[EE + e];
    } else {
        const int* p = (const int*)ei;
        s = p[e]; d = p[EE + e];
    }
}

__global__ void k_edge_deg(const void* __restrict__ ei, const float* __restrict__ ew) {
    int e = blockIdx.x * blockDim.x + threadIdx.x;
    if (e >= EE) return;
    int s, d; read_edge(ei, e, s, d);
    atomicAdd(&g_deg[s], ew[e]);
    atomicAdd(&g_cnt[d], 1);
}

__global__ void k_dinv() {
    int i = blockIdx.x * blockDim.x + threadIdx.x;
    if (i >= NN) return;
    float dg = g_deg[i];
    g_deg[i] = (dg > 0.f) ? rsqrtf(dg) : 0.f;
}

__global__ void k_scan() {
    const int T = 1024;
    int t = threadIdx.x;
    const int CH = (NN + T - 1) / T;
    int beg = t * CH;
    int end = beg + CH; if (end > NN) end = NN; if (beg > NN) beg = NN;
    int s = 0;
    for (int i = beg; i < end; i++) s += g_cnt[i];
    __shared__ int sm[T];
    sm[t] = s; __syncthreads();
    for (int off = 1; off < T; off <<= 1) {
        int v = (t >= off) ? sm[t - off] : 0;
        __syncthreads();
        sm[t] += v;
        __syncthreads();
    }
    int run = sm[t] - s;
    for (int i = beg; i < end; i++) {
        g_rowptr[i] = run; g_cursor[i] = run;
        run += g_cnt[i];
    }
    if (t == 0) g_rowptr[NN] = EE;
}

__global__ void k_fill(const void* __restrict__ ei, const float* __restrict__ ew) {
    int e = blockIdx.x * blockDim.x + threadIdx.x;
    if (e >= EE) return;
    int s, d; read_edge(ei, e, s, d);
    float nrm = ew[e] * g_deg[s] * g_deg[d];
    int pos = atomicAdd(&g_cursor[d], 1);
    g_csr_src[pos] = s;
    g_csr_nrm[pos] = nrm;
}

// ---------------- SpMM (fp16 gather, warp-per-row) -------------------------
// out[row] = A*v[row] + B*(sum_e nrm*vh[src_e]) + G*aux[row]

__device__ __forceinline__ void spmm_row(
    const __half2* __restrict__ vh,
    const float* __restrict__ v, const float* __restrict__ aux,
    float* __restrict__ out, __half2* __restrict__ outh,
    int row, int lane, float A, float B, float G)
{
    int beg = g_rowptr[row], end = g_rowptr[row + 1];
    float acc0 = 0.f, acc1 = 0.f, acc2 = 0.f, acc3 = 0.f;
    int e = beg;
    for (; e + 1 < end; e += 2) {
        int   s0 = g_csr_src[e],     s1 = g_csr_src[e + 1];
        float w0 = g_csr_nrm[e],     w1 = g_csr_nrm[e + 1];
        float2 r0 = __half22float2(vh[s0 * 32 + lane]);
        float2 r1 = __half22float2(vh[s1 * 32 + lane]);
        acc0 += w0 * r0.x;  acc1 += w0 * r0.y;
        acc2 += w1 * r1.x;  acc3 += w1 * r1.y;
    }
    if (e < end) {
        int s0 = g_csr_src[e]; float w0 = g_csr_nrm[e];
        float2 r0 = __half22float2(vh[s0 * 32 + lane]);
        acc0 += w0 * r0.x;  acc1 += w0 * r0.y;
    }
    acc0 += acc2; acc1 += acc3;
    int base = row * DD + lane * 2;
    float2 vc = *(const float2*)(v + base);
    float2 ax = *(const float2*)(aux + base);
    float2 o;
    o.x = A * vc.x + B * acc0 + G * ax.x;
    o.y = A * vc.y + B * acc1 + G * ax.y;
    *(float2*)(out + base) = o;
    if (outh) outh[row * 32 + lane] = __floats2half2_rn(o.x, o.y);
}

__global__ void __launch_bounds__(256) k_spmm1_XH(
    const float* __restrict__ X, const float* __restrict__ H,
    const float* __restrict__ lam)
{
    int warp = threadIdx.x >> 5, lane = threadIdx.x & 31;
    int row = blockIdx.x * 8 + warp;
    if (row >= NN) return;
    float c = 2.f / __ldg(lam);
    const __half2* vh = blockIdx.y ? g_H16 : g_X16;
    const float* v    = blockIdx.y ? H : X;
    float* out        = blockIdx.y ? g_TH1 : g_TX1;
    __half2* outh     = blockIdx.y ? g_TH1h : g_TX1h;
    spmm_row(vh, v, v, out, outh, row, lane, c - 1.f, -c, 0.f);
}

__global__ void __launch_bounds__(256) k_spmm2_XH(
    const float* __restrict__ X, const float* __restrict__ H,
    const float* __restrict__ lam)
{
    int warp = threadIdx.x >> 5, lane = threadIdx.x & 31;
    int row = blockIdx.x * 8 + warp;
    if (row >= NN) return;
    float c = 2.f / __ldg(lam);
    const __half2* vh = blockIdx.y ? g_TH1h : g_TX1h;
    const float* v    = blockIdx.y ? g_TH1 : g_TX1;
    const float* aux  = blockIdx.y ? H : X;
    float* out        = blockIdx.y ? g_TH2 : g_TX2;
    spmm_row(vh, v, aux, out, (__half2*)0, row, lane, 2.f * (c - 1.f), -2.f * c, -1.f);
}

__global__ void __launch_bounds__(256) k_spmm1_HR(const float* __restrict__ lam) {
    int warp = threadIdx.x >> 5, lane = threadIdx.x & 31;
    int row = blockIdx.x * 8 + warp;
    if (row >= NN) return;
    float c = 2.f / __ldg(lam);
    spmm_row(g_HRh, g_HR, g_HR, g_THR1, g_THR1h, row, lane, c - 1.f, -c, 0.f);
}

__global__ void __launch_bounds__(256) k_spmm2_HR(const float* __restrict__ lam) {
    int warp = threadIdx.x >> 5, lane = threadIdx.x & 31;
    int row = blockIdx.x * 8 + warp;
    if (row >= NN) return;
    float c = 2.f / __ldg(lam);
    spmm_row(g_THR1h, g_THR1, g_HR, g_THR2, (__half2*)0, row, lane, 2.f * (c - 1.f), -2.f * c, -1.f);
}

// ---------------- mma.sync bf16 GEMM (M=64 tile, 2 CTAs/SM) ----------------
// D[64, 64] per gate = sum over 192-K of (A0|A1|A2)[64,64] @ W^T, bf16 3-way
// error-corrected split: Ah*Bh + Ah*Bl + Al*Bh (fp32 accumulate).
// 8 warps = 4 row-groups x 2 N-halves.

__device__ __forceinline__ void mma16816(float* c, uint32_t a0, uint32_t a1,
                                         uint32_t a2, uint32_t a3,
                                         uint32_t b0, uint32_t b1) {
    asm volatile(
        "mma.sync.aligned.m16n8k16.row.col.f32.bf16.bf16.f32 "
        "{%0,%1,%2,%3}, {%4,%5,%6,%7}, {%8,%9}, {%0,%1,%2,%3};"
        : "+f"(c[0]), "+f"(c[1]), "+f"(c[2]), "+f"(c[3])
        : "r"(a0), "r"(a1), "r"(a2), "r"(a3), "r"(b0), "r"(b1));
}

#define ASTR 200                 // padded K stride (elements)
#define EL_AH 0
#define EL_AL 12800
#define EL_BH 25600
#define EL_BL 38400
#define DSM_BYTES (51200 * 2)    // 102400 B -> 2 CTAs/SM

// whichsel: 0 -> blockIdx.y picks which 0/1 ; 2 -> final HR gemm
__global__ void __launch_bounds__(256) k_gemm_mma(
    const float* __restrict__ Xin, const float* __restrict__ Hin, int whichsel)
{
    extern __shared__ unsigned short sm_el[];
    unsigned short* Ah = sm_el + EL_AH;
    unsigned short* Al = sm_el + EL_AL;
    unsigned short* Bh = sm_el + EL_BH;
    unsigned short* Bl = sm_el + EL_BL;

    int tid = threadIdx.x;
    int wid = tid >> 5, lane = tid & 31;
    int rowbase = blockIdx.x * 64;
    int which = (whichsel == 2) ? 2 : (int)blockIdx.y;

    const float *A0, *A1, *A2; float* Cbase; int gates, wstart, wstep;
    if (which == 0)      { A0 = Xin;  A1 = g_TX1;  A2 = g_TX2;  Cbase = g_GA; gates = 3; wstart = 0; wstep = 2; }
    else if (which == 1) { A0 = Hin;  A1 = g_TH1;  A2 = g_TH2;  Cbase = g_GB; gates = 2; wstart = 1; wstep = 2; }
    else                 { A0 = g_HR; A1 = g_THR1; A2 = g_THR2; Cbase = g_Hh; gates = 1; wstart = 5; wstep = 0; }

    // ---- stage A: 3 chunks (K=192), 64 rows, split into hi/lo bf16 ----
    for (int c = 0; c < 3; c++) {
        const float* Abuf = (c == 0) ? A0 : ((c == 1) ? A1 : A2);
        #pragma unroll
        for (int i = 0; i < 4; i++) {
            int lin = tid + i * 256;          // 1024 float4 units
            int m = lin >> 4;
            int kq = lin & 15;
            int grow = rowbase + m;
            float4 v = make_float4(0.f, 0.f, 0.f, 0.f);
            if (grow < NN) v = *(const float4*)(Abuf + (size_t)grow * DD + kq * 4);
            unsigned short h0, l0, h1, l1, h2, l2, h3, l3;
            split2(v.x, h0, l0); split2(v.y, h1, l1);
            split2(v.z, h2, l2); split2(v.w, h3, l3);
            uint2 hp, lp;
            hp.x = (uint32_t)h0 | ((uint32_t)h1 << 16);
            hp.y = (uint32_t)h2 | ((uint32_t)h3 << 16);
            lp.x = (uint32_t)l0 | ((uint32_t)l1 << 16);
            lp.y = (uint32_t)l2 | ((uint32_t)l3 << 16);
            int eo = m * ASTR + c * 64 + kq * 4;
            *(uint2*)(Ah + eo) = hp;
            *(uint2*)(Al + eo) = lp;
        }
    }
    __syncthreads();

    // fragment base pointers: warp = (row group rw 0..3) x (N half nh 0..1)
    int gq = lane >> 2, tg = lane & 3;
    int rw = wid & 3, nh = wid >> 2;
    int mrow = rw * 16;
    const uint32_t* pAh = (const uint32_t*)(Ah + (mrow + gq) * ASTR + tg * 2);
    const uint32_t* pAl = (const uint32_t*)(Al + (mrow + gq) * ASTR + tg * 2);
    const uint32_t* pBh0 = (const uint32_t*)(Bh + gq * ASTR + tg * 2) + nh * 3200;
    const uint32_t* pBl0 = (const uint32_t*)(Bl + gq * ASTR + tg * 2) + nh * 3200;

    for (int g = 0; g < gates; g++) {
        int wsel = wstart + g * wstep;
        // ---- stage B: copy pre-split transposed weights (uint4) ----
        #pragma unroll
        for (int c = 0; c < 3; c++) {
            int mat = wsel * 3 + c;
            const uint4* srcH = (const uint4*)(g_Wh + (mat << 12));
            const uint4* srcL = (const uint4*)(g_Wl + (mat << 12));
            #pragma unroll
            for (int i = 0; i < 2; i++) {
                int lin = tid + i * 256;      // 512 uint4 units: (d, k8)
                int d  = lin >> 3;
                int k8 = (lin & 7) * 8;
                int eo = d * ASTR + c * 64 + k8;
                *(uint4*)(Bh + eo) = srcH[lin];
                *(uint4*)(Bl + eo) = srcL[lin];
            }
        }
        __syncthreads();

        float acc[16];
        #pragma unroll
        for (int i = 0; i < 16; i++) acc[i] = 0.f;

        #pragma unroll 2
        for (int ks = 0; ks < 12; ks++) {
            int kw = ks * 8;
            uint32_t ah0 = pAh[kw], ah1 = pAh[kw + 800];
            uint32_t ah2 = pAh[kw + 4], ah3 = pAh[kw + 804];
            uint32_t al0 = pAl[kw], al1 = pAl[kw + 800];
            uint32_t al2 = pAl[kw + 4], al3 = pAl[kw + 804];
            #pragma unroll
            for (int nt = 0; nt < 4; nt++) {
                int bo = nt * 800 + kw;
                uint32_t bh0 = pBh0[bo], bh1 = pBh0[bo + 4];
                uint32_t bl0 = pBl0[bo], bl1 = pBl0[bo + 4];
                float* a = acc + nt * 4;
                mma16816(a, ah0, ah1, ah2, ah3, bh0, bh1);
                mma16816(a, ah0, ah1, ah2, ah3, bl0, bl1);
                mma16816(a, al0, al1, al2, al3, bh0, bh1);
            }
        }

        // ---- epilogue ----
        float* C = Cbase + (size_t)g * NND;
        int r0 = rowbase + mrow + gq;
        int r1 = r0 + 8;
        #pragma unroll
        for (int nt = 0; nt < 4; nt++) {
            int col = (nh * 4 + nt) * 8 + tg * 2;
            if (r0 < NN) *(float2*)(C + (size_t)r0 * DD + col) = make_float2(acc[nt*4+0], acc[nt*4+1]);
            if (r1 < NN) *(float2*)(C + (size_t)r1 * DD + col) = make_float2(acc[nt*4+2], acc[nt*4+3]);
        }
        __syncthreads();
    }
}

// ---------------- elementwise (float4) --------------------------------------

__global__ void k_ew1(const float* __restrict__ H, const float* __restrict__ B) {
    int i4 = blockIdx.x * blockDim.x + threadIdx.x;
    if (i4 >= NND / 4) return;
    int i = i4 * 4;
    int d = i & (DD - 1);
    float4 ga0 = *(const float4*)(g_GA + i);
    float4 gb0 = *(const float4*)(g_GB + i);
    float4 ga1 = *(const float4*)(g_GA + (size_t)NND + i);
    float4 gb1 = *(const float4*)(g_GB + (size_t)NND + i);
    float4 b0  = *(const float4*)(B + d);
    float4 b1  = *(const float4*)(B + 64 + d);
    float4 b2  = *(const float4*)(B + 128 + d);
    float4 b3  = *(const float4*)(B + 192 + d);
    float4 h   = *(const float4*)(H + i);
    float4 z, hr;
    {
        float zl = ga0.x + gb0.x + b0.x + b1.x;
        float rl = ga1.x + gb1.x + b2.x + b3.x;
        z.x = 1.f / (1.f + __expf(-zl));
        hr.x = h.x / (1.f + __expf(-rl));
    }
    {
        float zl = ga0.y + gb0.y + b0.y + b1.y;
        float rl = ga1.y + gb1.y + b2.y + b3.y;
        z.y = 1.f / (1.f + __expf(-zl));
        hr.y = h.y / (1.f + __expf(-rl));
    }
    {
        float zl = ga0.z + gb0.z + b0.z + b1.z;
        float rl = ga1.z + gb1.z + b2.z + b3.z;
        z.z = 1.f / (1.f + __expf(-zl));
        hr.z = h.z / (1.f + __expf(-rl));
    }
    {
        float zl = ga0.w + gb0.w + b0.w + b1.w;
        float rl = ga1.w + gb1.w + b2.w + b3.w;
        z.w = 1.f / (1.f + __expf(-zl));
        hr.w = h.w / (1.f + __expf(-rl));
    }
    *(float4*)(g_Z + i)  = z;
    *(float4*)(g_HR + i) = hr;
    g_HRh[i4 * 2]     = __floats2half2_rn(hr.x, hr.y);
    g_HRh[i4 * 2 + 1] = __floats2half2_rn(hr.z, hr.w);
}

__global__ void k_ew2(const float* __restrict__ H, const float* __restrict__ B,
                      float* __restrict__ out) {
    int i4 = blockIdx.x * blockDim.x + threadIdx.x;
    if (i4 >= NND / 4) return;
    int i = i4 * 4;
    int d = i & (DD - 1);
    float4 gx = *(const float4*)(g_GA + 2u * NND + i);
    float4 gh = *(const float4*)(g_Hh + i);
    float4 b0 = *(const float4*)(B + 256 + d);
    float4 b1 = *(const float4*)(B + 320 + d);
    float4 z  = *(const float4*)(g_Z + i);
    float4 h  = *(const float4*)(H + i);
    float4 o;
    o.x = z.x * tanhf(gx.x + gh.x + b0.x + b1.x) + (1.f - z.x) * h.x;
    o.y = z.y * tanhf(gx.y + gh.y + b0.y + b1.y) + (1.f - z.y) * h.y;
    o.z = z.z * tanhf(gx.z + gh.z + b0.z + b1.z) + (1.f - z.z) * h.z;
    o.w = z.w * tanhf(gx.w + gh.w + b0.w + b1.w) + (1.f - z.w) * h.w;
    *(float4*)(out + i) = o;
}

// ---------------- launch ----------------------------------------------------

extern "C" void kernel_launch(void* const* d_in, const int* in_sizes, int n_in,
                              void* d_out, int out_size) {
    const float* X   = (const float*)d_in[0];
    const void*  EI  = d_in[1];
    const float* EW  = (const float*)d_in[2];
    const float* H   = (const float*)d_in[3];
    const float* LAM = (const float*)d_in[4];
    const float* W   = (const float*)d_in[5];
    const float* B   = (const float*)d_in[6];
    float* OUT = (float*)d_out;

    (void)in_sizes; (void)n_in; (void)out_size;

    cudaFuncSetAttribute(k_gemm_mma, cudaFuncAttributeMaxDynamicSharedMemorySize, DSM_BYTES);

    // weight pre-split + fp16 tables + graph setup + CSR build
    k_detect<<<1, 32>>>((const unsigned int*)EI);
    k_tohalf<<<(NND / 2 + 255) / 256, 256>>>(X, H);
    k_wsplit<<<(18 * 4096 + 255) / 256, 256>>>(W);
    k_zero<<<(NN + 255) / 256, 256>>>();
    k_edge_deg<<<(EE + 255) / 256, 256>>>(EI, EW);
    k_dinv<<<(NN + 255) / 256, 256>>>();
    k_scan<<<1, 1024>>>();
    k_fill<<<(EE + 255) / 256, 256>>>(EI, EW);

    // Chebyshev propagation for X and H
    dim3 sg((NN + 7) / 8, 2);
    k_spmm1_XH<<<sg, 256>>>(X, H, LAM);
    k_spmm2_XH<<<sg, 256>>>(X, H, LAM);

    // merged tensor-core GEMMs for X-gates and H-gates
    int ntiles = (NN + 63) / 64;
    k_gemm_mma<<<dim3(ntiles, 2), 256, DSM_BYTES>>>(X, H, 0);

    // Z, R, HR
    k_ew1<<<(NND / 4 + 255) / 256, 256>>>(H, B);

    // propagation for HR, then final GEMM
    dim3 sh((NN + 7) / 8, 1);
    k_spmm1_HR<<<sh, 256>>>(LAM);
    k_spmm2_HR<<<sh, 256>>>(LAM);
    k_gemm_mma<<<dim3(ntiles, 1), 256, DSM_BYTES>>>(X, H, 2);

    // output gate
    k_ew2<<<(NND / 4 + 255) / 256, 256>>>(H, B, OUT);
}

// round 6
// speedup vs baseline: 1.5479x; 1.0157x over previous
#include <cuda_runtime.h>
#include <cuda_bf16.h>
#include <cuda_fp16.h>
#include <cstdint>

#define NN 50000
#define EE 800000
#define DD 64
#define NND (NN * DD)
#define NH (NND / 2)

// ---------------- scratch (device globals; no allocation allowed) ----------
__device__ float g_deg[NN];
__device__ int   g_cnt[NN];
__device__ int   g_rowptr[NN + 1];
__device__ int   g_cursor[NN];
__device__ int   g_csr_src[EE];
__device__ float g_csr_nrm[EE];

// fp32 (self/aux terms)
__device__ float g_TX1[NND], g_TH1[NND], g_HR[NND], g_THR1[NND];

// fp16 gather tables
__device__ __half2 g_X16[NH], g_H16[NH], g_TX1h[NH], g_TH1h[NH], g_HRh16[NH], g_THR1h[NH];

// bf16 hi/lo packed pairs (2 per uint32) for GEMM A operands
__device__ uint32_t g_hX[NH],   g_lX[NH],   g_hH[NH],   g_lH[NH];
__device__ uint32_t g_hTX1[NH], g_lTX1[NH], g_hTX2[NH], g_lTX2[NH];
__device__ uint32_t g_hTH1[NH], g_lTH1[NH], g_hTH2[NH], g_lTH2[NH];
__device__ uint32_t g_hHR[NH],  g_lHR[NH],  g_hTHR1[NH], g_lTHR1[NH], g_hTHR2[NH], g_lTHR2[NH];

__device__ float g_GA[3u * NND];        // Zx, Rx, Hx
__device__ float g_GB[2u * NND];        // Zh, Rh
__device__ float g_Z [NND];

// pre-split weights, transposed to [mat][dout][kin], bf16 hi/lo
__device__ unsigned short g_Wh[18 * 4096];
__device__ unsigned short g_Wl[18 * 4096];

__device__ int   g_idx64;

// ---------------- helpers ---------------------------------------------------

__device__ __forceinline__ void split2(float x, unsigned short& h, unsigned short& l) {
    __nv_bfloat16 hb = __float2bfloat16_rn(x);
    float r = x - __bfloat162float(hb);
    __nv_bfloat16 lb = __float2bfloat16_rn(r);
    h = *(unsigned short*)&hb;
    l = *(unsigned short*)&lb;
}

__device__ __forceinline__ void splitpack(float2 v, uint32_t& hi, uint32_t& lo) {
    unsigned short h0, l0, h1, l1;
    split2(v.x, h0, l0); split2(v.y, h1, l1);
    hi = (uint32_t)h0 | ((uint32_t)h1 << 16);
    lo = (uint32_t)l0 | ((uint32_t)l1 << 16);
}

// ---------------- setup: detect + zero + fp16/bf16 tables + wsplit ---------

__global__ void k_setup(const unsigned int* __restrict__ ei,
                        const float* __restrict__ X, const float* __restrict__ Hm,
                        const float* __restrict__ W) {
    int i = blockIdx.x * blockDim.x + threadIdx.x;
    if (blockIdx.x == 0 && threadIdx.x < 32) {
        unsigned v = ei[2 * threadIdx.x + 1];
        unsigned ball = __ballot_sync(0xffffffffu, v == 0u);
        if (threadIdx.x == 0) g_idx64 = (ball == 0xffffffffu) ? 1 : 0;
    }
    if (i < NN) { g_deg[i] = 0.f; g_cnt[i] = 0; }
    if (i < 18 * 4096) {
        int mat = i >> 12, kin = (i >> 6) & 63, dout = i & 63;
        unsigned short h, l;
        split2(W[i], h, l);
        int o = (mat << 12) | (dout << 6) | kin;
        g_Wh[o] = h;
        g_Wl[o] = l;
    }
    if (i < NH) {
        float2 x = ((const float2*)X)[i];
        float2 h = ((const float2*)Hm)[i];
        g_X16[i] = __floats2half2_rn(x.x, x.y);
        g_H16[i] = __floats2half2_rn(h.x, h.y);
        splitpack(x, g_hX[i], g_lX[i]);
        splitpack(h, g_hH[i], g_lH[i]);
    }
}

__device__ __forceinline__ void read_edge(const void* ei, int e, int& s, int& d) {
    if (g_idx64) {
        const long long* p = (const long long*)ei;
        s = (int)p[e]; d = (int)p[EE + e];
    } else {
        const int* p = (const int*)ei;
        s = p[e]; d = p[EE + e];
    }
}

__global__ void k_edge_deg(const void* __restrict__ ei, const float* __restrict__ ew) {
    int e = blockIdx.x * blockDim.x + threadIdx.x;
    if (e >= EE) return;
    int s, d; read_edge(ei, e, s, d);
    atomicAdd(&g_deg[s], ew[e]);
    atomicAdd(&g_cnt[d], 1);
}

__global__ void k_scan() {
    const int T = 1024;
    int t = threadIdx.x;
    const int CH = (NN + T - 1) / T;
    int beg = t * CH;
    int end = beg + CH; if (end > NN) end = NN; if (beg > NN) beg = NN;
    int s = 0;
    for (int i = beg; i < end; i++) s += g_cnt[i];
    __shared__ int sm[T];
    sm[t] = s; __syncthreads();
    for (int off = 1; off < T; off <<= 1) {
        int v = (t >= off) ? sm[t - off] : 0;
        __syncthreads();
        sm[t] += v;
        __syncthreads();
    }
    int run = sm[t] - s;
    for (int i = beg; i < end; i++) {
        g_rowptr[i] = run; g_cursor[i] = run;
        run += g_cnt[i];
    }
    if (t == 0) g_rowptr[NN] = EE;
}

__global__ void k_fill(const void* __restrict__ ei, const float* __restrict__ ew) {
    int e = blockIdx.x * blockDim.x + threadIdx.x;
    if (e >= EE) return;
    int s, d; read_edge(ei, e, s, d);
    float ds = g_deg[s], dd = g_deg[d];
    float is = (ds > 0.f) ? rsqrtf(ds) : 0.f;
    float id = (dd > 0.f) ? rsqrtf(dd) : 0.f;
    float nrm = ew[e] * is * id;
    int pos = atomicAdd(&g_cursor[d], 1);
    g_csr_src[pos] = s;
    g_csr_nrm[pos] = nrm;
}

// ---------------- SpMM (fp16 gather, warp-per-row) -------------------------

// fused 2-matrix row: oM = A*vM[row] + Bc*gather(vM16) + G*auxM[row]
__device__ __forceinline__ void spmm_row2(
    const __half2* __restrict__ vA16, const __half2* __restrict__ vB16,
    const float* __restrict__ vA, const float* __restrict__ vB,
    const float* __restrict__ auxA, const float* __restrict__ auxB,
    int row, int lane, float A, float Bc, float G,
    float2& oA, float2& oB)
{
    int beg = g_rowptr[row], end = g_rowptr[row + 1];
    float aA0 = 0.f, aA1 = 0.f, aB0 = 0.f, aB1 = 0.f;
    float cA0 = 0.f, cA1 = 0.f, cB0 = 0.f, cB1 = 0.f;
    int e = beg;
    for (; e + 1 < end; e += 2) {
        int   s0 = g_csr_src[e],  s1 = g_csr_src[e + 1];
        float w0 = g_csr_nrm[e],  w1 = g_csr_nrm[e + 1];
        float2 xa0 = __half22float2(vA16[s0 * 32 + lane]);
        float2 xb0 = __half22float2(vB16[s0 * 32 + lane]);
        float2 xa1 = __half22float2(vA16[s1 * 32 + lane]);
        float2 xb1 = __half22float2(vB16[s1 * 32 + lane]);
        aA0 += w0 * xa0.x;  aA1 += w0 * xa0.y;
        aB0 += w0 * xb0.x;  aB1 += w0 * xb0.y;
        cA0 += w1 * xa1.x;  cA1 += w1 * xa1.y;
        cB0 += w1 * xb1.x;  cB1 += w1 * xb1.y;
    }
    if (e < end) {
        int s0 = g_csr_src[e]; float w0 = g_csr_nrm[e];
        float2 xa0 = __half22float2(vA16[s0 * 32 + lane]);
        float2 xb0 = __half22float2(vB16[s0 * 32 + lane]);
        aA0 += w0 * xa0.x;  aA1 += w0 * xa0.y;
        aB0 += w0 * xb0.x;  aB1 += w0 * xb0.y;
    }
    aA0 += cA0; aA1 += cA1; aB0 += cB0; aB1 += cB1;
    int base = row * DD + lane * 2;
    float2 va = *(const float2*)(vA + base);
    float2 vb = *(const float2*)(vB + base);
    float2 xa = *(const float2*)(auxA + base);
    float2 xb = *(const float2*)(auxB + base);
    oA.x = A * va.x + Bc * aA0 + G * xa.x;
    oA.y = A * va.y + Bc * aA1 + G * xa.y;
    oB.x = A * vb.x + Bc * aB0 + G * xb.x;
    oB.y = A * vb.y + Bc * aB1 + G * xb.y;
}

// single-matrix row
__device__ __forceinline__ void spmm_row1(
    const __half2* __restrict__ v16,
    const float* __restrict__ v, const float* __restrict__ aux,
    int row, int lane, float A, float Bc, float G, float2& o)
{
    int beg = g_rowptr[row], end = g_rowptr[row + 1];
    float a0 = 0.f, a1 = 0.f, c0 = 0.f, c1 = 0.f;
    int e = beg;
    for (; e + 1 < end; e += 2) {
        int   s0 = g_csr_src[e],  s1 = g_csr_src[e + 1];
        float w0 = g_csr_nrm[e],  w1 = g_csr_nrm[e + 1];
        float2 x0 = __half22float2(v16[s0 * 32 + lane]);
        float2 x1 = __half22float2(v16[s1 * 32 + lane]);
        a0 += w0 * x0.x;  a1 += w0 * x0.y;
        c0 += w1 * x1.x;  c1 += w1 * x1.y;
    }
    if (e < end) {
        int s0 = g_csr_src[e]; float w0 = g_csr_nrm[e];
        float2 x0 = __half22float2(v16[s0 * 32 + lane]);
        a0 += w0 * x0.x;  a1 += w0 * x0.y;
    }
    a0 += c0; a1 += c1;
    int base = row * DD + lane * 2;
    float2 vc = *(const float2*)(v + base);
    float2 ax = *(const float2*)(aux + base);
    o.x = A * vc.x + Bc * a0 + G * ax.x;
    o.y = A * vc.y + Bc * a1 + G * ax.y;
}

__global__ void __launch_bounds__(256) k_spmm1_XH(
    const float* __restrict__ X, const float* __restrict__ Hm,
    const float* __restrict__ lam)
{
    int warp = threadIdx.x >> 5, lane = threadIdx.x & 31;
    int row = blockIdx.x * 8 + warp;
    if (row >= NN) return;
    float c = 2.f / __ldg(lam);
    float2 oX, oH;
    spmm_row2(g_X16, g_H16, X, Hm, X, Hm, row, lane, c - 1.f, -c, 0.f, oX, oH);
    int b32 = row * 32 + lane;
    *(float2*)(g_TX1 + row * DD + lane * 2) = oX;
    *(float2*)(g_TH1 + row * DD + lane * 2) = oH;
    g_TX1h[b32] = __floats2half2_rn(oX.x, oX.y);
    g_TH1h[b32] = __floats2half2_rn(oH.x, oH.y);
    splitpack(oX, g_hTX1[b32], g_lTX1[b32]);
    splitpack(oH, g_hTH1[b32], g_lTH1[b32]);
}

__global__ void __launch_bounds__(256) k_spmm2_XH(
    const float* __restrict__ X, const float* __restrict__ Hm,
    const float* __restrict__ lam)
{
    int warp = threadIdx.x >> 5, lane = threadIdx.x & 31;
    int row = blockIdx.x * 8 + warp;
    if (row >= NN) return;
    float c = 2.f / __ldg(lam);
    float2 oX, oH;
    spmm_row2(g_TX1h, g_TH1h, g_TX1, g_TH1, X, Hm, row, lane,
              2.f * (c - 1.f), -2.f * c, -1.f, oX, oH);
    int b32 = row * 32 + lane;
    splitpack(oX, g_hTX2[b32], g_lTX2[b32]);
    splitpack(oH, g_hTH2[b32], g_lTH2[b32]);
}

__global__ void __launch_bounds__(256) k_spmm1_HR(const float* __restrict__ lam) {
    int warp = threadIdx.x >> 5, lane = threadIdx.x & 31;
    int row = blockIdx.x * 8 + warp;
    if (row >= NN) return;
    float c = 2.f / __ldg(lam);
    float2 o;
    spmm_row1(g_HRh16, g_HR, g_HR, row, lane, c - 1.f, -c, 0.f, o);
    int b32 = row * 32 + lane;
    *(float2*)(g_THR1 + row * DD + lane * 2) = o;
    g_THR1h[b32] = __floats2half2_rn(o.x, o.y);
    splitpack(o, g_hTHR1[b32], g_lTHR1[b32]);
}

__global__ void __launch_bounds__(256) k_spmm2_HR(const float* __restrict__ lam) {
    int warp = threadIdx.x >> 5, lane = threadIdx.x & 31;
    int row = blockIdx.x * 8 + warp;
    if (row >= NN) return;
    float c = 2.f / __ldg(lam);
    float2 o;
    spmm_row1(g_THR1h, g_THR1, g_HR, row, lane, 2.f * (c - 1.f), -2.f * c, -1.f, o);
    int b32 = row * 32 + lane;
    splitpack(o, g_hTHR2[b32], g_lTHR2[b32]);
}

// ---------------- mma.sync bf16 GEMM (M=64 tile, 2 CTAs/SM) ----------------
// A-stage is pure uint4 copies (A pre-split at production time).
// which=2 fuses the output-gate elementwise into the epilogue.

__device__ __forceinline__ void mma16816(float* c, uint32_t a0, uint32_t a1,
                                         uint32_t a2, uint32_t a3,
                                         uint32_t b0, uint32_t b1) {
    asm volatile(
        "mma.sync.aligned.m16n8k16.row.col.f32.bf16.bf16.f32 "
        "{%0,%1,%2,%3}, {%4,%5,%6,%7}, {%8,%9}, {%0,%1,%2,%3};"
        : "+f"(c[0]), "+f"(c[1]), "+f"(c[2]), "+f"(c[3])
        : "r"(a0), "r"(a1), "r"(a2), "r"(a3), "r"(b0), "r"(b1));
}

#define ASTR 200                 // padded K stride (elements)
#define EL_AH 0
#define EL_AL 12800
#define EL_BH 25600
#define EL_BL 38400
#define DSM_BYTES (51200 * 2)    // 102400 B -> 2 CTAs/SM

__global__ void __launch_bounds__(256) k_gemm_mma(
    const float* __restrict__ Hm, const float* __restrict__ Bb,
    float* __restrict__ OUT, int whichsel)
{
    extern __shared__ unsigned short sm_el[];
    unsigned short* Ah = sm_el + EL_AH;
    unsigned short* Al = sm_el + EL_AL;
    unsigned short* Bh = sm_el + EL_BH;
    unsigned short* Bl = sm_el + EL_BL;

    int tid = threadIdx.x;
    int wid = tid >> 5, lane = tid & 31;
    int rowbase = blockIdx.x * 64;
    int which = (whichsel == 2) ? 2 : (int)blockIdx.y;

    const uint32_t *hs0, *hs1, *hs2, *ls0, *ls1, *ls2;
    float* Cbase; int gates, wstart, wstep;
    if (which == 0)      { hs0 = g_hX;  hs1 = g_hTX1;  hs2 = g_hTX2;
                           ls0 = g_lX;  ls1 = g_lTX1;  ls2 = g_lTX2;
                           Cbase = g_GA; gates = 3; wstart = 0; wstep = 2; }
    else if (which == 1) { hs0 = g_hH;  hs1 = g_hTH1;  hs2 = g_hTH2;
                           ls0 = g_lH;  ls1 = g_lTH1;  ls2 = g_lTH2;
                           Cbase = g_GB; gates = 2; wstart = 1; wstep = 2; }
    else                 { hs0 = g_hHR; hs1 = g_hTHR1; hs2 = g_hTHR2;
                           ls0 = g_lHR; ls1 = g_lTHR1; ls2 = g_lTHR2;
                           Cbase = 0;   gates = 1; wstart = 5; wstep = 0; }

    // ---- stage A: pure uint4 copies of pre-split chunks ----
    {
        const uint32_t* hsel[3] = { hs0, hs1, hs2 };
        const uint32_t* lsel[3] = { ls0, ls1, ls2 };
        #pragma unroll
        for (int c = 0; c < 3; c++) {
            const uint4* sH = (const uint4*)hsel[c];
            const uint4* sL = (const uint4*)lsel[c];
            #pragma unroll
            for (int i = 0; i < 2; i++) {
                int lin = tid + i * 256;      // 512 uint4 units: (m, k8)
                int m = lin >> 3;
                int k8 = lin & 7;
                int grow = rowbase + m;
                uint4 vh = make_uint4(0, 0, 0, 0), vl = make_uint4(0, 0, 0, 0);
                if (grow < NN) { vh = sH[grow * 8 + k8]; vl = sL[grow * 8 + k8]; }
                int eo = m * ASTR + c * 64 + k8 * 8;
                *(uint4*)(Ah + eo) = vh;
                *(uint4*)(Al + eo) = vl;
            }
        }
    }
    __syncthreads();

    // fragment base pointers: warp = (row group rw 0..3) x (N half nh 0..1)
    int gq = lane >> 2, tg = lane & 3;
    int rw = wid & 3, nh = wid >> 2;
    int mrow = rw * 16;
    const uint32_t* pAh = (const uint32_t*)(Ah + (mrow + gq) * ASTR + tg * 2);
    const uint32_t* pAl = (const uint32_t*)(Al + (mrow + gq) * ASTR + tg * 2);
    const uint32_t* pBh0 = (const uint32_t*)(Bh + gq * ASTR + tg * 2) + nh * 3200;
    const uint32_t* pBl0 = (const uint32_t*)(Bl + gq * ASTR + tg * 2) + nh * 3200;

    for (int g = 0; g < gates; g++) {
        int wsel = wstart + g * wstep;
        // ---- stage B: copy pre-split transposed weights (uint4) ----
        #pragma unroll
        for (int c = 0; c < 3; c++) {
            int mat = wsel * 3 + c;
            const uint4* srcH = (const uint4*)(g_Wh + (mat << 12));
            const uint4* srcL = (const uint4*)(g_Wl + (mat << 12));
            #pragma unroll
            for (int i = 0; i < 2; i++) {
                int lin = tid + i * 256;
                int d  = lin >> 3;
                int k8 = (lin & 7) * 8;
                int eo = d * ASTR + c * 64 + k8;
                *(uint4*)(Bh + eo) = srcH[lin];
                *(uint4*)(Bl + eo) = srcL[lin];
            }
        }
        __syncthreads();

        float acc[16];
        #pragma unroll
        for (int i = 0; i < 16; i++) acc[i] = 0.f;

        #pragma unroll 2
        for (int ks = 0; ks < 12; ks++) {
            int kw = ks * 8;
            uint32_t ah0 = pAh[kw], ah1 = pAh[kw + 800];
            uint32_t ah2 = pAh[kw + 4], ah3 = pAh[kw + 804];
            uint32_t al0 = pAl[kw], al1 = pAl[kw + 800];
            uint32_t al2 = pAl[kw + 4], al3 = pAl[kw + 804];
            #pragma unroll
            for (int nt = 0; nt < 4; nt++) {
                int bo = nt * 800 + kw;
                uint32_t bh0 = pBh0[bo], bh1 = pBh0[bo + 4];
                uint32_t bl0 = pBl0[bo], bl1 = pBl0[bo + 4];
                float* a = acc + nt * 4;
                mma16816(a, ah0, ah1, ah2, ah3, bh0, bh1);
                mma16816(a, ah0, ah1, ah2, ah3, bl0, bl1);
                mma16816(a, al0, al1, al2, al3, bh0, bh1);
            }
        }

        // ---- epilogue ----
        int r0 = rowbase + mrow + gq;
        int r1 = r0 + 8;
        if (whichsel != 2) {
            float* C = Cbase + (size_t)g * NND;
            #pragma unroll
            for (int nt = 0; nt < 4; nt++) {
                int col = (nh * 4 + nt) * 8 + tg * 2;
                if (r0 < NN) *(float2*)(C + (size_t)r0 * DD + col) = make_float2(acc[nt*4+0], acc[nt*4+1]);
                if (r1 < NN) *(float2*)(C + (size_t)r1 * DD + col) = make_float2(acc[nt*4+2], acc[nt*4+3]);
            }
        } else {
            // fused output gate: out = z*tanh(Hx + acc + b4 + b5) + (1-z)*h
            #pragma unroll
            for (int nt = 0; nt < 4; nt++) {
                int col = (nh * 4 + nt) * 8 + tg * 2;
                float bs0 = __ldg(Bb + 256 + col)     + __ldg(Bb + 320 + col);
                float bs1 = __ldg(Bb + 256 + col + 1) + __ldg(Bb + 320 + col + 1);
                if (r0 < NN) {
                    size_t o = (size_t)r0 * DD + col;
                    float2 gx = *(const float2*)(g_GA + 2u * NND + o);
                    float2 z  = *(const float2*)(g_Z + o);
                    float2 h  = *(const float2*)(Hm + o);
                    float2 ov;
                    ov.x = z.x * tanhf(gx.x + acc[nt*4+0] + bs0) + (1.f - z.x) * h.x;
                    ov.y = z.y * tanhf(gx.y + acc[nt*4+1] + bs1) + (1.f - z.y) * h.y;
                    *(float2*)(OUT + o) = ov;
                }
                if (r1 < NN) {
                    size_t o = (size_t)r1 * DD + col;
                    float2 gx = *(const float2*)(g_GA + 2u * NND + o);
                    float2 z  = *(const float2*)(g_Z + o);
                    float2 h  = *(const float2*)(Hm + o);
                    float2 ov;
                    ov.x = z.x * tanhf(gx.x + acc[nt*4+2] + bs0) + (1.f - z.x) * h.x;
                    ov.y = z.y * tanhf(gx.y + acc[nt*4+3] + bs1) + (1.f - z.y) * h.y;
                    *(float2*)(OUT + o) = ov;
                }
            }
        }
        if (g + 1 < gates) __syncthreads();
    }
}

// ---------------- elementwise: Z, R, HR (+ HR tables) -----------------------

__global__ void k_ew1(const float* __restrict__ Hm, const float* __restrict__ Bb) {
    int i4 = blockIdx.x * blockDim.x + threadIdx.x;
    if (i4 >= NND / 4) return;
    int i = i4 * 4;
    int d = i & (DD - 1);
    float4 ga0 = *(const float4*)(g_GA + i);
    float4 gb0 = *(const float4*)(g_GB + i);
    float4 ga1 = *(const float4*)(g_GA + (size_t)NND + i);
    float4 gb1 = *(const float4*)(g_GB + (size_t)NND + i);
    float4 b0  = *(const float4*)(Bb + d);
    float4 b1  = *(const float4*)(Bb + 64 + d);
    float4 b2  = *(const float4*)(Bb + 128 + d);
    float4 b3  = *(const float4*)(Bb + 192 + d);
    float4 h   = *(const float4*)(Hm + i);
    float4 z, hr;
    z.x = 1.f / (1.f + __expf(-(ga0.x + gb0.x + b0.x + b1.x)));
    z.y = 1.f / (1.f + __expf(-(ga0.y + gb0.y + b0.y + b1.y)));
    z.z = 1.f / (1.f + __expf(-(ga0.z + gb0.z + b0.z + b1.z)));
    z.w = 1.f / (1.f + __expf(-(ga0.w + gb0.w + b0.w + b1.w)));
    hr.x = h.x / (1.f + __expf(-(ga1.x + gb1.x + b2.x + b3.x)));
    hr.y = h.y / (1.f + __expf(-(ga1.y + gb1.y + b2.y + b3.y)));
    hr.z = h.z / (1.f + __expf(-(ga1.z + gb1.z + b2.z + b3.z)));
    hr.w = h.w / (1.f + __expf(-(ga1.w + gb1.w + b2.w + b3.w)));
    *(float4*)(g_Z + i)  = z;
    *(float4*)(g_HR + i) = hr;
    g_HRh16[i4 * 2]     = __floats2half2_rn(hr.x, hr.y);
    g_HRh16[i4 * 2 + 1] = __floats2half2_rn(hr.z, hr.w);
    splitpack(make_float2(hr.x, hr.y), g_hHR[i4 * 2],     g_lHR[i4 * 2]);
    splitpack(make_float2(hr.z, hr.w), g_hHR[i4 * 2 + 1], g_lHR[i4 * 2 + 1]);
}

// ---------------- launch ----------------------------------------------------

extern "C" void kernel_launch(void* const* d_in, const int* in_sizes, int n_in,
                              void* d_out, int out_size) {
    const float* X   = (const float*)d_in[0];
    const void*  EI  = d_in[1];
    const float* EW  = (const float*)d_in[2];
    const float* H   = (const float*)d_in[3];
    const float* LAM = (const float*)d_in[4];
    const float* W   = (const float*)d_in[5];
    const float* B   = (const float*)d_in[6];
    float* OUT = (float*)d_out;

    (void)in_sizes; (void)n_in; (void)out_size;

    cudaFuncSetAttribute(k_gemm_mma, cudaFuncAttributeMaxDynamicSharedMemorySize, DSM_BYTES);

    k_setup<<<(NH + 255) / 256, 256>>>((const unsigned int*)EI, X, H, W);
    k_edge_deg<<<(EE + 255) / 256, 256>>>(EI, EW);
    k_scan<<<1, 1024>>>();
    k_fill<<<(EE + 255) / 256, 256>>>(EI, EW);   // profiled slot (index 3)

    dim3 sg((NN + 7) / 8);
    k_spmm1_XH<<<sg, 256>>>(X, H, LAM);
    k_spmm2_XH<<<sg, 256>>>(X, H, LAM);

    int ntiles = (NN + 63) / 64;
    k_gemm_mma<<<dim3(ntiles, 2), 256, DSM_BYTES>>>(H, B, OUT, 0);

    k_ew1<<<(NND / 4 + 255) / 256, 256>>>(H, B);

    k_spmm1_HR<<<sg, 256>>>(LAM);
    k_spmm2_HR<<<sg, 256>>>(LAM);
    k_gemm_mma<<<dim3(ntiles, 1), 256, DSM_BYTES>>>(H, B, OUT, 2);
}

// round 7
// speedup vs baseline: 1.5944x; 1.0300x over previous
#include <cuda_runtime.h>
#include <cuda_bf16.h>
#include <cuda_fp16.h>
#include <cstdint>

#define NN 50000
#define EE 800000
#define DD 64
#define NND (NN * DD)
#define NH (NND / 2)

// ---------------- scratch (device globals; no allocation allowed) ----------
__device__ float g_deg[NN];          // zero-init (BSS); re-zeroed by k_ew1
__device__ int   g_cnt[NN];          // zero-init (BSS); re-zeroed by k_ew1
__device__ int   g_rowptr[NN + 1];
__device__ int   g_cursor[NN];
__device__ int2  g_csrE[EE];         // (src, nrm as int)

// fp32 (self/aux terms)
__device__ float g_TX1[NND], g_TH1[NND], g_HR[NND], g_THR1[NND];

// interleaved fp16 gather tables: entry (row*32+lane) = {X-pair, H-pair}
__device__ uint2 g_XHt[NN * 32];
__device__ uint2 g_T1t[NN * 32];
// single fp16 tables for HR chain
__device__ uint32_t g_HRh16[NH], g_THR1h[NH];

// bf16 hi/lo packed pairs (2 per uint32) for GEMM A operands
__device__ uint32_t g_hX[NH],   g_lX[NH],   g_hH[NH],   g_lH[NH];
__device__ uint32_t g_hTX1[NH], g_lTX1[NH], g_hTX2[NH], g_lTX2[NH];
__device__ uint32_t g_hTH1[NH], g_lTH1[NH], g_hTH2[NH], g_lTH2[NH];
__device__ uint32_t g_hHR[NH],  g_lHR[NH],  g_hTHR1[NH], g_lTHR1[NH], g_hTHR2[NH], g_lTHR2[NH];

__device__ float g_GA[3u * NND];        // Zx, Rx, Hx
__device__ float g_GB[2u * NND];        // Zh, Rh
__device__ float g_Z [NND];

// pre-split weights, transposed to [mat][dout][kin], bf16 hi/lo
__device__ unsigned short g_Wh[18 * 4096];
__device__ unsigned short g_Wl[18 * 4096];

// ---------------- helpers ---------------------------------------------------

__device__ __forceinline__ void split2(float x, unsigned short& h, unsigned short& l) {
    __nv_bfloat16 hb = __float2bfloat16_rn(x);
    float r = x - __bfloat162float(hb);
    __nv_bfloat16 lb = __float2bfloat16_rn(r);
    h = *(unsigned short*)&hb;
    l = *(unsigned short*)&lb;
}

__device__ __forceinline__ void splitpack(float2 v, uint32_t& hi, uint32_t& lo) {
    unsigned short h0, l0, h1, l1;
    split2(v.x, h0, l0); split2(v.y, h1, l1);
    hi = (uint32_t)h0 | ((uint32_t)h1 << 16);
    lo = (uint32_t)l0 | ((uint32_t)l1 << 16);
}

__device__ __forceinline__ uint32_t packh2(float2 v) {
    __half2 h = __floats2half2_rn(v.x, v.y);
    return *(uint32_t*)&h;
}

// block-local int64-layout detection: all warps read the same 32 words, so
// every warp computes the same answer; no cross-block state needed.
__device__ __forceinline__ int detect_idx64(const unsigned int* ei) {
    unsigned v = ei[2 * (threadIdx.x & 31) + 1];
    unsigned ball = __ballot_sync(0xffffffffu, v == 0u);
    return ball == 0xffffffffu;
}

__device__ __forceinline__ void read_edge(const void* ei, int idx64, int e, int& s, int& d) {
    if (idx64) {
        const long long* p = (const long long*)ei;
        s = (int)p[e]; d = (int)p[EE + e];
    } else {
        const int* p = (const int*)ei;
        s = p[e]; d = p[EE + e];
    }
}

// ---------------- launch 0: degree + count --------------------------------

__global__ void k_edge_deg(const void* __restrict__ ei, const float* __restrict__ ew) {
    int idx64 = detect_idx64((const unsigned int*)ei);
    int e = blockIdx.x * blockDim.x + threadIdx.x;
    if (e >= EE) return;
    int s, d; read_edge(ei, idx64, e, s, d);
    atomicAdd(&g_deg[s], ew[e]);
    atomicAdd(&g_cnt[d], 1);
}

// ---------------- launch 1: exclusive scan ---------------------------------

__global__ void k_scan() {
    const int T = 1024;
    int t = threadIdx.x;
    const int CH = (NN + T - 1) / T;
    int beg = t * CH;
    int end = beg + CH; if (end > NN) end = NN; if (beg > NN) beg = NN;
    int s = 0;
    for (int i = beg; i < end; i++) s += g_cnt[i];
    __shared__ int sm[T];
    sm[t] = s; __syncthreads();
    for (int off = 1; off < T; off <<= 1) {
        int v = (t >= off) ? sm[t - off] : 0;
        __syncthreads();
        sm[t] += v;
        __syncthreads();
    }
    int run = sm[t] - s;
    for (int i = beg; i < end; i++) {
        g_rowptr[i] = run; g_cursor[i] = run;
        run += g_cnt[i];
    }
    if (t == 0) g_rowptr[NN] = EE;
}

// ---------------- launch 2: CSR fill + gather tables + weight split --------

__global__ void k_fillsetup(const void* __restrict__ ei, const float* __restrict__ ew,
                            const float* __restrict__ X, const float* __restrict__ Hm,
                            const float* __restrict__ W) {
    int i = blockIdx.x * blockDim.x + threadIdx.x;
    if (i < EE) {
        int idx64 = detect_idx64((const unsigned int*)ei);
        int s, d; read_edge(ei, idx64, i, s, d);
        float ds = g_deg[s], dd = g_deg[d];
        float is = (ds > 0.f) ? rsqrtf(ds) : 0.f;
        float id = (dd > 0.f) ? rsqrtf(dd) : 0.f;
        float nrm = ew[i] * is * id;
        int pos = atomicAdd(&g_cursor[d], 1);
        g_csrE[pos] = make_int2(s, __float_as_int(nrm));
    }
    if (i < NH) {
        float2 x = ((const float2*)X)[i];
        float2 h = ((const float2*)Hm)[i];
        g_XHt[i] = make_uint2(packh2(x), packh2(h));
        splitpack(x, g_hX[i], g_lX[i]);
        splitpack(h, g_hH[i], g_lH[i]);
    }
    if (i < 18 * 4096) {
        int mat = i >> 12, kin = (i >> 6) & 63, dout = i & 63;
        unsigned short h, l;
        split2(W[i], h, l);
        int o = (mat << 12) | (dout << 6) | kin;
        g_Wh[o] = h;
        g_Wl[o] = l;
    }
}

// ---------------- SpMM gathers ----------------------------------------------

// fused 2-matrix gather from interleaved table (unroll 4, dual chains)
__device__ __forceinline__ void gather2(const uint2* __restrict__ tab, int row, int lane,
    float& rX0, float& rX1, float& rH0, float& rH1)
{
    int beg = g_rowptr[row], end = g_rowptr[row + 1];
    float aX0 = 0.f, aX1 = 0.f, aH0 = 0.f, aH1 = 0.f;
    float bX0 = 0.f, bX1 = 0.f, bH0 = 0.f, bH1 = 0.f;
    int e = beg;
    for (; e + 3 < end; e += 4) {
        int2 m0 = g_csrE[e],     m1 = g_csrE[e + 1];
        int2 m2 = g_csrE[e + 2], m3 = g_csrE[e + 3];
        uint2 t0 = tab[m0.x * 32 + lane];
        uint2 t1 = tab[m1.x * 32 + lane];
        uint2 t2 = tab[m2.x * 32 + lane];
        uint2 t3 = tab[m3.x * 32 + lane];
        float w0 = __int_as_float(m0.y), w1 = __int_as_float(m1.y);
        float w2 = __int_as_float(m2.y), w3 = __int_as_float(m3.y);
        float2 v;
        v = __half22float2(*(__half2*)&t0.x); aX0 += w0 * v.x; aX1 += w0 * v.y;
        v = __half22float2(*(__half2*)&t0.y); aH0 += w0 * v.x; aH1 += w0 * v.y;
        v = __half22float2(*(__half2*)&t1.x); bX0 += w1 * v.x; bX1 += w1 * v.y;
        v = __half22float2(*(__half2*)&t1.y); bH0 += w1 * v.x; bH1 += w1 * v.y;
        v = __half22float2(*(__half2*)&t2.x); aX0 += w2 * v.x; aX1 += w2 * v.y;
        v = __half22float2(*(__half2*)&t2.y); aH0 += w2 * v.x; aH1 += w2 * v.y;
        v = __half22float2(*(__half2*)&t3.x); bX0 += w3 * v.x; bX1 += w3 * v.y;
        v = __half22float2(*(__half2*)&t3.y); bH0 += w3 * v.x; bH1 += w3 * v.y;
    }
    for (; e < end; e++) {
        int2 m = g_csrE[e];
        uint2 t = tab[m.x * 32 + lane];
        float w = __int_as_float(m.y);
        float2 v;
        v = __half22float2(*(__half2*)&t.x); aX0 += w * v.x; aX1 += w * v.y;
        v = __half22float2(*(__half2*)&t.y); aH0 += w * v.x; aH1 += w * v.y;
    }
    rX0 = aX0 + bX0; rX1 = aX1 + bX1;
    rH0 = aH0 + bH0; rH1 = aH1 + bH1;
}

// single-matrix gather from half2 table (unroll 4, dual chains)
__device__ __forceinline__ void gather1(const uint32_t* __restrict__ tab, int row, int lane,
    float& r0, float& r1)
{
    int beg = g_rowptr[row], end = g_rowptr[row + 1];
    float a0 = 0.f, a1 = 0.f, b0 = 0.f, b1 = 0.f;
    int e = beg;
    for (; e + 3 < end; e += 4) {
        int2 m0 = g_csrE[e],     m1 = g_csrE[e + 1];
        int2 m2 = g_csrE[e + 2], m3 = g_csrE[e + 3];
        uint32_t t0 = tab[m0.x * 32 + lane];
        uint32_t t1 = tab[m1.x * 32 + lane];
        uint32_t t2 = tab[m2.x * 32 + lane];
        uint32_t t3 = tab[m3.x * 32 + lane];
        float w0 = __int_as_float(m0.y), w1 = __int_as_float(m1.y);
        float w2 = __int_as_float(m2.y), w3 = __int_as_float(m3.y);
        float2 v;
        v = __half22float2(*(__half2*)&t0); a0 += w0 * v.x; a1 += w0 * v.y;
        v = __half22float2(*(__half2*)&t1); b0 += w1 * v.x; b1 += w1 * v.y;
        v = __half22float2(*(__half2*)&t2); a0 += w2 * v.x; a1 += w2 * v.y;
        v = __half22float2(*(__half2*)&t3); b0 += w3 * v.x; b1 += w3 * v.y;
    }
    for (; e < end; e++) {
        int2 m = g_csrE[e];
        uint32_t t = tab[m.x * 32 + lane];
        float w = __int_as_float(m.y);
        float2 v = __half22float2(*(__half2*)&t);
        a0 += w * v.x; a1 += w * v.y;
    }
    r0 = a0 + b0; r1 = a1 + b1;
}

// launch 3 (profiled slot): T1 for X and H
__global__ void __launch_bounds__(256) k_spmm1_XH(
    const float* __restrict__ X, const float* __restrict__ Hm,
    const float* __restrict__ lam)
{
    int warp = threadIdx.x >> 5, lane = threadIdx.x & 31;
    int row = blockIdx.x * 8 + warp;
    if (row >= NN) return;
    float c = 2.f / __ldg(lam);
    float A = c - 1.f, Bc = -c;
    float rX0, rX1, rH0, rH1;
    gather2(g_XHt, row, lane, rX0, rX1, rH0, rH1);
    int base = row * DD + lane * 2;
    int b32 = row * 32 + lane;
    float2 vx = *(const float2*)(X + base);
    float2 vh = *(const float2*)(Hm + base);
    float2 oX = make_float2(A * vx.x + Bc * rX0, A * vx.y + Bc * rX1);
    float2 oH = make_float2(A * vh.x + Bc * rH0, A * vh.y + Bc * rH1);
    *(float2*)(g_TX1 + base) = oX;
    *(float2*)(g_TH1 + base) = oH;
    g_T1t[b32] = make_uint2(packh2(oX), packh2(oH));
    splitpack(oX, g_hTX1[b32], g_lTX1[b32]);
    splitpack(oH, g_hTH1[b32], g_lTH1[b32]);
}

// launch 4: T2 for X and H
__global__ void __launch_bounds__(256) k_spmm2_XH(
    const float* __restrict__ X, const float* __restrict__ Hm,
    const float* __restrict__ lam)
{
    int warp = threadIdx.x >> 5, lane = threadIdx.x & 31;
    int row = blockIdx.x * 8 + warp;
    if (row >= NN) return;
    float c = 2.f / __ldg(lam);
    float A = 2.f * (c - 1.f), Bc = -2.f * c;
    float rX0, rX1, rH0, rH1;
    gather2(g_T1t, row, lane, rX0, rX1, rH0, rH1);
    int base = row * DD + lane * 2;
    int b32 = row * 32 + lane;
    float2 vx = *(const float2*)(g_TX1 + base);
    float2 vh = *(const float2*)(g_TH1 + base);
    float2 xx = *(const float2*)(X + base);
    float2 xh = *(const float2*)(Hm + base);
    float2 oX = make_float2(A * vx.x + Bc * rX0 - xx.x, A * vx.y + Bc * rX1 - xx.y);
    float2 oH = make_float2(A * vh.x + Bc * rH0 - xh.x, A * vh.y + Bc * rH1 - xh.y);
    splitpack(oX, g_hTX2[b32], g_lTX2[b32]);
    splitpack(oH, g_hTH2[b32], g_lTH2[b32]);
}

__global__ void __launch_bounds__(256) k_spmm1_HR(const float* __restrict__ lam) {
    int warp = threadIdx.x >> 5, lane = threadIdx.x & 31;
    int row = blockIdx.x * 8 + warp;
    if (row >= NN) return;
    float c = 2.f / __ldg(lam);
    float A = c - 1.f, Bc = -c;
    float r0, r1;
    gather1(g_HRh16, row, lane, r0, r1);
    int base = row * DD + lane * 2;
    int b32 = row * 32 + lane;
    float2 v = *(const float2*)(g_HR + base);
    float2 o = make_float2(A * v.x + Bc * r0, A * v.y + Bc * r1);
    *(float2*)(g_THR1 + base) = o;
    g_THR1h[b32] = packh2(o);
    splitpack(o, g_hTHR1[b32], g_lTHR1[b32]);
}

__global__ void __launch_bounds__(256) k_spmm2_HR(const float* __restrict__ lam) {
    int warp = threadIdx.x >> 5, lane = threadIdx.x & 31;
    int row = blockIdx.x * 8 + warp;
    if (row >= NN) return;
    float c = 2.f / __ldg(lam);
    float A = 2.f * (c - 1.f), Bc = -2.f * c;
    float r0, r1;
    gather1(g_THR1h, row, lane, r0, r1);
    int base = row * DD + lane * 2;
    int b32 = row * 32 + lane;
    float2 v = *(const float2*)(g_THR1 + base);
    float2 h = *(const float2*)(g_HR + base);
    float2 o = make_float2(A * v.x + Bc * r0 - h.x, A * v.y + Bc * r1 - h.y);
    splitpack(o, g_hTHR2[b32], g_lTHR2[b32]);
}

// ---------------- mma.sync bf16 GEMM (M=64 tile, 2 CTAs/SM) ----------------

__device__ __forceinline__ void mma16816(float* c, uint32_t a0, uint32_t a1,
                                         uint32_t a2, uint32_t a3,
                                         uint32_t b0, uint32_t b1) {
    asm volatile(
        "mma.sync.aligned.m16n8k16.row.col.f32.bf16.bf16.f32 "
        "{%0,%1,%2,%3}, {%4,%5,%6,%7}, {%8,%9}, {%0,%1,%2,%3};"
        : "+f"(c[0]), "+f"(c[1]), "+f"(c[2]), "+f"(c[3])
        : "r"(a0), "r"(a1), "r"(a2), "r"(a3), "r"(b0), "r"(b1));
}

#define ASTR 200
#define EL_AH 0
#define EL_AL 12800
#define EL_BH 25600
#define EL_BL 38400
#define DSM_BYTES (51200 * 2)

__global__ void __launch_bounds__(256) k_gemm_mma(
    const float* __restrict__ Hm, const float* __restrict__ Bb,
    float* __restrict__ OUT, int whichsel)
{
    extern __shared__ unsigned short sm_el[];
    unsigned short* Ah = sm_el + EL_AH;
    unsigned short* Al = sm_el + EL_AL;
    unsigned short* Bh = sm_el + EL_BH;
    unsigned short* Bl = sm_el + EL_BL;

    int tid = threadIdx.x;
    int wid = tid >> 5, lane = tid & 31;
    int rowbase = blockIdx.x * 64;
    int which = (whichsel == 2) ? 2 : (int)blockIdx.y;

    const uint32_t *hs0, *hs1, *hs2, *ls0, *ls1, *ls2;
    float* Cbase; int gates, wstart, wstep;
    if (which == 0)      { hs0 = g_hX;  hs1 = g_hTX1;  hs2 = g_hTX2;
                           ls0 = g_lX;  ls1 = g_lTX1;  ls2 = g_lTX2;
                           Cbase = g_GA; gates = 3; wstart = 0; wstep = 2; }
    else if (which == 1) { hs0 = g_hH;  hs1 = g_hTH1;  hs2 = g_hTH2;
                           ls0 = g_lH;  ls1 = g_lTH1;  ls2 = g_lTH2;
                           Cbase = g_GB; gates = 2; wstart = 1; wstep = 2; }
    else                 { hs0 = g_hHR; hs1 = g_hTHR1; hs2 = g_hTHR2;
                           ls0 = g_lHR; ls1 = g_lTHR1; ls2 = g_lTHR2;
                           Cbase = 0;   gates = 1; wstart = 5; wstep = 0; }

    {
        const uint32_t* hsel[3] = { hs0, hs1, hs2 };
        const uint32_t* lsel[3] = { ls0, ls1, ls2 };
        #pragma unroll
        for (int c = 0; c < 3; c++) {
            const uint4* sH = (const uint4*)hsel[c];
            const uint4* sL = (const uint4*)lsel[c];
            #pragma unroll
            for (int i = 0; i < 2; i++) {
                int lin = tid + i * 256;
                int m = lin >> 3;
                int k8 = lin & 7;
                int grow = rowbase + m;
                uint4 vh = make_uint4(0, 0, 0, 0), vl = make_uint4(0, 0, 0, 0);
                if (grow < NN) { vh = sH[grow * 8 + k8]; vl = sL[grow * 8 + k8]; }
                int eo = m * ASTR + c * 64 + k8 * 8;
                *(uint4*)(Ah + eo) = vh;
                *(uint4*)(Al + eo) = vl;
            }
        }
    }
    __syncthreads();

    int gq = lane >> 2, tg = lane & 3;
    int rw = wid & 3, nh = wid >> 2;
    int mrow = rw * 16;
    const uint32_t* pAh = (const uint32_t*)(Ah + (mrow + gq) * ASTR + tg * 2);
    const uint32_t* pAl = (const uint32_t*)(Al + (mrow + gq) * ASTR + tg * 2);
    const uint32_t* pBh0 = (const uint32_t*)(Bh + gq * ASTR + tg * 2) + nh * 3200;
    const uint32_t* pBl0 = (const uint32_t*)(Bl + gq * ASTR + tg * 2) + nh * 3200;

    for (int g = 0; g < gates; g++) {
        int wsel = wstart + g * wstep;
        #pragma unroll
        for (int c = 0; c < 3; c++) {
            int mat = wsel * 3 + c;
            const uint4* srcH = (const uint4*)(g_Wh + (mat << 12));
            const uint4* srcL = (const uint4*)(g_Wl + (mat << 12));
            #pragma unroll
            for (int i = 0; i < 2; i++) {
                int lin = tid + i * 256;
                int d  = lin >> 3;
                int k8 = (lin & 7) * 8;
                int eo = d * ASTR + c * 64 + k8;
                *(uint4*)(Bh + eo) = srcH[lin];
                *(uint4*)(Bl + eo) = srcL[lin];
            }
        }
        __syncthreads();

        float acc[16];
        #pragma unroll
        for (int i = 0; i < 16; i++) acc[i] = 0.f;

        #pragma unroll 2
        for (int ks = 0; ks < 12; ks++) {
            int kw = ks * 8;
            uint32_t ah0 = pAh[kw], ah1 = pAh[kw + 800];
            uint32_t ah2 = pAh[kw + 4], ah3 = pAh[kw + 804];
            uint32_t al0 = pAl[kw], al1 = pAl[kw + 800];
            uint32_t al2 = pAl[kw + 4], al3 = pAl[kw + 804];
            #pragma unroll
            for (int nt = 0; nt < 4; nt++) {
                int bo = nt * 800 + kw;
                uint32_t bh0 = pBh0[bo], bh1 = pBh0[bo + 4];
                uint32_t bl0 = pBl0[bo], bl1 = pBl0[bo + 4];
                float* a = acc + nt * 4;
                mma16816(a, ah0, ah1, ah2, ah3, bh0, bh1);
                mma16816(a, ah0, ah1, ah2, ah3, bl0, bl1);
                mma16816(a, al0, al1, al2, al3, bh0, bh1);
            }
        }

        int r0 = rowbase + mrow + gq;
        int r1 = r0 + 8;
        if (whichsel != 2) {
            float* C = Cbase + (size_t)g * NND;
            #pragma unroll
            for (int nt = 0; nt < 4; nt++) {
                int col = (nh * 4 + nt) * 8 + tg * 2;
                if (r0 < NN) *(float2*)(C + (size_t)r0 * DD + col) = make_float2(acc[nt*4+0], acc[nt*4+1]);
                if (r1 < NN) *(float2*)(C + (size_t)r1 * DD + col) = make_float2(acc[nt*4+2], acc[nt*4+3]);
            }
        } else {
            #pragma unroll
            for (int nt = 0; nt < 4; nt++) {
                int col = (nh * 4 + nt) * 8 + tg * 2;
                float bs0 = __ldg(Bb + 256 + col)     + __ldg(Bb + 320 + col);
                float bs1 = __ldg(Bb + 256 + col + 1) + __ldg(Bb + 320 + col + 1);
                if (r0 < NN) {
                    size_t o = (size_t)r0 * DD + col;
                    float2 gx = *(const float2*)(g_GA + 2u * NND + o);
                    float2 z  = *(const float2*)(g_Z + o);
                    float2 h  = *(const float2*)(Hm + o);
                    float2 ov;
                    ov.x = z.x * tanhf(gx.x + acc[nt*4+0] + bs0) + (1.f - z.x) * h.x;
                    ov.y = z.y * tanhf(gx.y + acc[nt*4+1] + bs1) + (1.f - z.y) * h.y;
                    *(float2*)(OUT + o) = ov;
                }
                if (r1 < NN) {
                    size_t o = (size_t)r1 * DD + col;
                    float2 gx = *(const float2*)(g_GA + 2u * NND + o);
                    float2 z  = *(const float2*)(g_Z + o);
                    float2 h  = *(const float2*)(Hm + o);
                    float2 ov;
                    ov.x = z.x * tanhf(gx.x + acc[nt*4+2] + bs0) + (1.f - z.x) * h.x;
                    ov.y = z.y * tanhf(gx.y + acc[nt*4+3] + bs1) + (1.f - z.y) * h.y;
                    *(float2*)(OUT + o) = ov;
                }
            }
        }
        if (g + 1 < gates) __syncthreads();
    }
}

// ---------------- elementwise: Z, R, HR (+ tables) + next-replay reset ------

__global__ void k_ew1(const float* __restrict__ Hm, const float* __restrict__ Bb) {
    int i4 = blockIdx.x * blockDim.x + threadIdx.x;
    if (i4 >= NND / 4) return;
    if (i4 < NN) { g_deg[i4] = 0.f; g_cnt[i4] = 0; }   // reset for next replay
    int i = i4 * 4;
    int d = i & (DD - 1);
    float4 ga0 = *(const float4*)(g_GA + i);
    float4 gb0 = *(const float4*)(g_GB + i);
    float4 ga1 = *(const float4*)(g_GA + (size_t)NND + i);
    float4 gb1 = *(const float4*)(g_GB + (size_t)NND + i);
    float4 b0  = *(const float4*)(Bb + d);
    float4 b1  = *(const float4*)(Bb + 64 + d);
    float4 b2  = *(const float4*)(Bb + 128 + d);
    float4 b3  = *(const float4*)(Bb + 192 + d);
    float4 h   = *(const float4*)(Hm + i);
    float4 z, hr;
    z.x = 1.f / (1.f + __expf(-(ga0.x + gb0.x + b0.x + b1.x)));
    z.y = 1.f / (1.f + __expf(-(ga0.y + gb0.y + b0.y + b1.y)));
    z.z = 1.f / (1.f + __expf(-(ga0.z + gb0.z + b0.z + b1.z)));
    z.w = 1.f / (1.f + __expf(-(ga0.w + gb0.w + b0.w + b1.w)));
    hr.x = h.x / (1.f + __expf(-(ga1.x + gb1.x + b2.x + b3.x)));
    hr.y = h.y / (1.f + __expf(-(ga1.y + gb1.y + b2.y + b3.y)));
    hr.z = h.z / (1.f + __expf(-(ga1.z + gb1.z + b2.z + b3.z)));
    hr.w = h.w / (1.f + __expf(-(ga1.w + gb1.w + b2.w + b3.w)));
    *(float4*)(g_Z + i)  = z;
    *(float4*)(g_HR + i) = hr;
    g_HRh16[i4 * 2]     = packh2(make_float2(hr.x, hr.y));
    g_HRh16[i4 * 2 + 1] = packh2(make_float2(hr.z, hr.w));
    splitpack(make_float2(hr.x, hr.y), g_hHR[i4 * 2],     g_lHR[i4 * 2]);
    splitpack(make_float2(hr.z, hr.w), g_hHR[i4 * 2 + 1], g_lHR[i4 * 2 + 1]);
}

// ---------------- launch ----------------------------------------------------

extern "C" void kernel_launch(void* const* d_in, const int* in_sizes, int n_in,
                              void* d_out, int out_size) {
    const float* X   = (const float*)d_in[0];
    const void*  EI  = d_in[1];
    const float* EW  = (const float*)d_in[2];
    const float* H   = (const float*)d_in[3];
    const float* LAM = (const float*)d_in[4];
    const float* W   = (const float*)d_in[5];
    const float* B   = (const float*)d_in[6];
    float* OUT = (float*)d_out;

    (void)in_sizes; (void)n_in; (void)out_size;

    cudaFuncSetAttribute(k_gemm_mma, cudaFuncAttributeMaxDynamicSharedMemorySize, DSM_BYTES);

    k_edge_deg<<<(EE + 255) / 256, 256>>>(EI, EW);                   // 0
    k_scan<<<1, 1024>>>();                                           // 1
    k_fillsetup<<<(NH + 255) / 256, 256>>>(EI, EW, X, H, W);         // 2

    dim3 sg((NN + 7) / 8);
    k_spmm1_XH<<<sg, 256>>>(X, H, LAM);                              // 3 (profiled)
    k_spmm2_XH<<<sg, 256>>>(X, H, LAM);                              // 4

    int ntiles = (NN + 63) / 64;
    k_gemm_mma<<<dim3(ntiles, 2), 256, DSM_BYTES>>>(H, B, OUT, 0);   // 5

    k_ew1<<<(NND / 4 + 255) / 256, 256>>>(H, B);                     // 6

    k_spmm1_HR<<<sg, 256>>>(LAM);                                    // 7
    k_spmm2_HR<<<sg, 256>>>(LAM);                                    // 8
    k_gemm_mma<<<dim3(ntiles, 1), 256, DSM_BYTES>>>(H, B, OUT, 2);   // 9
}

// round 8
// speedup vs baseline: 1.6156x; 1.0133x over previous
#include <cuda_runtime.h>
#include <cuda_fp16.h>
#include <cstdint>

#define NN 50000
#define EE 800000
#define DD 64
#define NND (NN * DD)
#define NH (NND / 2)

// ---------------- scratch (device globals; no allocation allowed) ----------
__device__ float g_deg[NN];          // zero-init (BSS); re-zeroed by k_ew1
__device__ int   g_cnt[NN];          // zero-init (BSS); re-zeroed by k_ew1
__device__ int   g_rowptr[NN + 1];
__device__ int   g_cursor[NN];
__device__ int2  g_csrE[EE];         // (src, nrm as int)

// unified fp16 hi/lo tables, word = fp16 pair (2 dims). [row*32+lane]
// interleaved X/H chain: uint2 = {X word, H word}
__device__ uint2 g_XHt[NN * 32],  g_XHlo[NN * 32];   // X,H      (fillsetup)
__device__ uint2 g_T1t[NN * 32],  g_T1lo[NN * 32];   // TX1,TH1  (spmm1)
__device__ uint2 g_T2t[NN * 32],  g_T2lo[NN * 32];   // TX2,TH2  (spmm2)
// HR chain: single words
__device__ uint32_t g_HRt[NN * 32],   g_HRlo[NN * 32];    // ew1
__device__ uint32_t g_THR1t[NN * 32], g_THR1lo[NN * 32];  // spmm1_HR
__device__ uint32_t g_THR2t[NN * 32], g_THR2lo[NN * 32];  // spmm2_HR

__device__ float g_GA[3u * NND];        // Zx, Rx, Hx
__device__ float g_GB[2u * NND];        // Zh, Rh
__device__ float g_Z [NND];

// pre-split weights, transposed to [mat][dout][kin], fp16 hi/lo
__device__ unsigned short g_Wh[18 * 4096];
__device__ unsigned short g_Wl[18 * 4096];

// ---------------- helpers ---------------------------------------------------

__device__ __forceinline__ void fsplit(float x, unsigned short& h, unsigned short& l) {
    __half hh = __float2half_rn(x);
    float r = x - __half2float(hh);
    __half ll = __float2half_rn(r);
    h = *(unsigned short*)&hh;
    l = *(unsigned short*)&ll;
}

__device__ __forceinline__ void fsplitpack(float2 v, uint32_t& hi, uint32_t& lo) {
    unsigned short h0, l0, h1, l1;
    fsplit(v.x, h0, l0); fsplit(v.y, h1, l1);
    hi = (uint32_t)h0 | ((uint32_t)h1 << 16);
    lo = (uint32_t)l0 | ((uint32_t)l1 << 16);
}

__device__ __forceinline__ float2 rec2(uint32_t h, uint32_t l) {
    float2 a = __half22float2(*(__half2*)&h);
    float2 b = __half22float2(*(__half2*)&l);
    return make_float2(a.x + b.x, a.y + b.y);
}

__device__ __forceinline__ int detect_idx64(const unsigned int* ei) {
    unsigned v = ei[2 * (threadIdx.x & 31) + 1];
    unsigned ball = __ballot_sync(0xffffffffu, v == 0u);
    return ball == 0xffffffffu;
}

__device__ __forceinline__ void read_edge(const void* ei, int idx64, int e, int& s, int& d) {
    if (idx64) {
        const long long* p = (const long long*)ei;
        s = (int)p[e]; d = (int)p[EE + e];
    } else {
        const int* p = (const int*)ei;
        s = p[e]; d = p[EE + e];
    }
}

// ---------------- launch 0: degree + count ---------------------------------

__global__ void k_edge_deg(const void* __restrict__ ei, const float* __restrict__ ew) {
    int idx64 = detect_idx64((const unsigned int*)ei);
    int e = blockIdx.x * blockDim.x + threadIdx.x;
    if (e >= EE) return;
    int s, d; read_edge(ei, idx64, e, s, d);
    atomicAdd(&g_deg[s], ew[e]);
    atomicAdd(&g_cnt[d], 1);
}

// ---------------- launch 1: exclusive scan ---------------------------------

__global__ void k_scan() {
    const int T = 1024;
    int t = threadIdx.x;
    const int CH = (NN + T - 1) / T;
    int beg = t * CH;
    int end = beg + CH; if (end > NN) end = NN; if (beg > NN) beg = NN;
    int s = 0;
    for (int i = beg; i < end; i++) s += g_cnt[i];
    __shared__ int sm[T];
    sm[t] = s; __syncthreads();
    for (int off = 1; off < T; off <<= 1) {
        int v = (t >= off) ? sm[t - off] : 0;
        __syncthreads();
        sm[t] += v;
        __syncthreads();
    }
    int run = sm[t] - s;
    for (int i = beg; i < end; i++) {
        g_rowptr[i] = run; g_cursor[i] = run;
        run += g_cnt[i];
    }
    if (t == 0) g_rowptr[NN] = EE;
}

// ---------------- launch 2: CSR fill + tables + weight split ---------------

__global__ void k_fillsetup(const void* __restrict__ ei, const float* __restrict__ ew,
                            const float* __restrict__ X, const float* __restrict__ Hm,
                            const float* __restrict__ W) {
    int i = blockIdx.x * blockDim.x + threadIdx.x;
    if (i < EE) {
        int idx64 = detect_idx64((const unsigned int*)ei);
        int s, d; read_edge(ei, idx64, i, s, d);
        float ds = g_deg[s], dd = g_deg[d];
        float is = (ds > 0.f) ? rsqrtf(ds) : 0.f;
        float id = (dd > 0.f) ? rsqrtf(dd) : 0.f;
        float nrm = ew[i] * is * id;
        int pos = atomicAdd(&g_cursor[d], 1);
        g_csrE[pos] = make_int2(s, __float_as_int(nrm));
    }
    if (i < NH) {
        float2 x = ((const float2*)X)[i];
        float2 h = ((const float2*)Hm)[i];
        uint32_t hx, lx, hh, lh;
        fsplitpack(x, hx, lx);
        fsplitpack(h, hh, lh);
        g_XHt[i]  = make_uint2(hx, hh);
        g_XHlo[i] = make_uint2(lx, lh);
    }
    if (i < 18 * 4096) {
        int mat = i >> 12, kin = (i >> 6) & 63, dout = i & 63;
        unsigned short h, l;
        fsplit(W[i], h, l);
        int o = (mat << 12) | (dout << 6) | kin;
        g_Wh[o] = h;
        g_Wl[o] = l;
    }
}

// ---------------- SpMM gathers ----------------------------------------------

// fused 2-matrix gather from interleaved hi table (unroll 4, dual chains)
__device__ __forceinline__ void gather2(const uint2* __restrict__ tab, int row, int lane,
    float& rX0, float& rX1, float& rH0, float& rH1)
{
    int beg = g_rowptr[row], end = g_rowptr[row + 1];
    float aX0 = 0.f, aX1 = 0.f, aH0 = 0.f, aH1 = 0.f;
    float bX0 = 0.f, bX1 = 0.f, bH0 = 0.f, bH1 = 0.f;
    int e = beg;
    for (; e + 3 < end; e += 4) {
        int2 m0 = g_csrE[e],     m1 = g_csrE[e + 1];
        int2 m2 = g_csrE[e + 2], m3 = g_csrE[e + 3];
        uint2 t0 = tab[m0.x * 32 + lane];
        uint2 t1 = tab[m1.x * 32 + lane];
        uint2 t2 = tab[m2.x * 32 + lane];
        uint2 t3 = tab[m3.x * 32 + lane];
        float w0 = __int_as_float(m0.y), w1 = __int_as_float(m1.y);
        float w2 = __int_as_float(m2.y), w3 = __int_as_float(m3.y);
        float2 v;
        v = __half22float2(*(__half2*)&t0.x); aX0 += w0 * v.x; aX1 += w0 * v.y;
        v = __half22float2(*(__half2*)&t0.y); aH0 += w0 * v.x; aH1 += w0 * v.y;
        v = __half22float2(*(__half2*)&t1.x); bX0 += w1 * v.x; bX1 += w1 * v.y;
        v = __half22float2(*(__half2*)&t1.y); bH0 += w1 * v.x; bH1 += w1 * v.y;
        v = __half22float2(*(__half2*)&t2.x); aX0 += w2 * v.x; aX1 += w2 * v.y;
        v = __half22float2(*(__half2*)&t2.y); aH0 += w2 * v.x; aH1 += w2 * v.y;
        v = __half22float2(*(__half2*)&t3.x); bX0 += w3 * v.x; bX1 += w3 * v.y;
        v = __half22float2(*(__half2*)&t3.y); bH0 += w3 * v.x; bH1 += w3 * v.y;
    }
    for (; e < end; e++) {
        int2 m = g_csrE[e];
        uint2 t = tab[m.x * 32 + lane];
        float w = __int_as_float(m.y);
        float2 v;
        v = __half22float2(*(__half2*)&t.x); aX0 += w * v.x; aX1 += w * v.y;
        v = __half22float2(*(__half2*)&t.y); aH0 += w * v.x; aH1 += w * v.y;
    }
    rX0 = aX0 + bX0; rX1 = aX1 + bX1;
    rH0 = aH0 + bH0; rH1 = aH1 + bH1;
}

// single-matrix gather (unroll 4, dual chains)
__device__ __forceinline__ void gather1(const uint32_t* __restrict__ tab, int row, int lane,
    float& r0, float& r1)
{
    int beg = g_rowptr[row], end = g_rowptr[row + 1];
    float a0 = 0.f, a1 = 0.f, b0 = 0.f, b1 = 0.f;
    int e = beg;
    for (; e + 3 < end; e += 4) {
        int2 m0 = g_csrE[e],     m1 = g_csrE[e + 1];
        int2 m2 = g_csrE[e + 2], m3 = g_csrE[e + 3];
        uint32_t t0 = tab[m0.x * 32 + lane];
        uint32_t t1 = tab[m1.x * 32 + lane];
        uint32_t t2 = tab[m2.x * 32 + lane];
        uint32_t t3 = tab[m3.x * 32 + lane];
        float w0 = __int_as_float(m0.y), w1 = __int_as_float(m1.y);
        float w2 = __int_as_float(m2.y), w3 = __int_as_float(m3.y);
        float2 v;
        v = __half22float2(*(__half2*)&t0); a0 += w0 * v.x; a1 += w0 * v.y;
        v = __half22float2(*(__half2*)&t1); b0 += w1 * v.x; b1 += w1 * v.y;
        v = __half22float2(*(__half2*)&t2); a0 += w2 * v.x; a1 += w2 * v.y;
        v = __half22float2(*(__half2*)&t3); b0 += w3 * v.x; b1 += w3 * v.y;
    }
    for (; e < end; e++) {
        int2 m = g_csrE[e];
        uint32_t t = tab[m.x * 32 + lane];
        float w = __int_as_float(m.y);
        float2 v = __half22float2(*(__half2*)&t);
        a0 += w * v.x; a1 += w * v.y;
    }
    r0 = a0 + b0; r1 = a1 + b1;
}

// launch 3 (profiled slot): T1 for X and H
__global__ void __launch_bounds__(256) k_spmm1_XH(const float* __restrict__ lam) {
    int warp = threadIdx.x >> 5, lane = threadIdx.x & 31;
    int row = blockIdx.x * 8 + warp;
    if (row >= NN) return;
    float c = 2.f / __ldg(lam);
    float A = c - 1.f, Bc = -c;
    float rX0, rX1, rH0, rH1;
    gather2(g_XHt, row, lane, rX0, rX1, rH0, rH1);
    int b32 = row * 32 + lane;
    uint2 th = g_XHt[b32], tl = g_XHlo[b32];
    float2 vx = rec2(th.x, tl.x);
    float2 vh = rec2(th.y, tl.y);
    float2 oX = make_float2(A * vx.x + Bc * rX0, A * vx.y + Bc * rX1);
    float2 oH = make_float2(A * vh.x + Bc * rH0, A * vh.y + Bc * rH1);
    uint32_t hx, lx, hh, lh;
    fsplitpack(oX, hx, lx);
    fsplitpack(oH, hh, lh);
    g_T1t[b32]  = make_uint2(hx, hh);
    g_T1lo[b32] = make_uint2(lx, lh);
}

// launch 4: T2 for X and H
__global__ void __launch_bounds__(256) k_spmm2_XH(const float* __restrict__ lam) {
    int warp = threadIdx.x >> 5, lane = threadIdx.x & 31;
    int row = blockIdx.x * 8 + warp;
    if (row >= NN) return;
    float c = 2.f / __ldg(lam);
    float A = 2.f * (c - 1.f), Bc = -2.f * c;
    float rX0, rX1, rH0, rH1;
    gather2(g_T1t, row, lane, rX0, rX1, rH0, rH1);
    int b32 = row * 32 + lane;
    uint2 sh = g_T1t[b32], sl = g_T1lo[b32];
    uint2 ah = g_XHt[b32], al = g_XHlo[b32];
    float2 vx = rec2(sh.x, sl.x), vh = rec2(sh.y, sl.y);
    float2 xx = rec2(ah.x, al.x), xh = rec2(ah.y, al.y);
    float2 oX = make_float2(A * vx.x + Bc * rX0 - xx.x, A * vx.y + Bc * rX1 - xx.y);
    float2 oH = make_float2(A * vh.x + Bc * rH0 - xh.x, A * vh.y + Bc * rH1 - xh.y);
    uint32_t hx, lx, hh, lh;
    fsplitpack(oX, hx, lx);
    fsplitpack(oH, hh, lh);
    g_T2t[b32]  = make_uint2(hx, hh);
    g_T2lo[b32] = make_uint2(lx, lh);
}

__global__ void __launch_bounds__(256) k_spmm1_HR(const float* __restrict__ lam) {
    int warp = threadIdx.x >> 5, lane = threadIdx.x & 31;
    int row = blockIdx.x * 8 + warp;
    if (row >= NN) return;
    float c = 2.f / __ldg(lam);
    float A = c - 1.f, Bc = -c;
    float r0, r1;
    gather1(g_HRt, row, lane, r0, r1);
    int b32 = row * 32 + lane;
    float2 v = rec2(g_HRt[b32], g_HRlo[b32]);
    float2 o = make_float2(A * v.x + Bc * r0, A * v.y + Bc * r1);
    uint32_t h, l;
    fsplitpack(o, h, l);
    g_THR1t[b32]  = h;
    g_THR1lo[b32] = l;
}

__global__ void __launch_bounds__(256) k_spmm2_HR(const float* __restrict__ lam) {
    int warp = threadIdx.x >> 5, lane = threadIdx.x & 31;
    int row = blockIdx.x * 8 + warp;
    if (row >= NN) return;
    float c = 2.f / __ldg(lam);
    float A = 2.f * (c - 1.f), Bc = -2.f * c;
    float r0, r1;
    gather1(g_THR1t, row, lane, r0, r1);
    int b32 = row * 32 + lane;
    float2 v = rec2(g_THR1t[b32], g_THR1lo[b32]);
    float2 h = rec2(g_HRt[b32], g_HRlo[b32]);
    float2 o = make_float2(A * v.x + Bc * r0 - h.x, A * v.y + Bc * r1 - h.y);
    uint32_t hh, ll;
    fsplitpack(o, hh, ll);
    g_THR2t[b32]  = hh;
    g_THR2lo[b32] = ll;
}

// ---------------- mma.sync fp16 GEMM (M=64 tile, 2 CTAs/SM) ----------------
// hi/lo split: Ah*Bh + Ah*Bl + Al*Bh, fp32 accumulate.

__device__ __forceinline__ void mma16816(float* c, uint32_t a0, uint32_t a1,
                                         uint32_t a2, uint32_t a3,
                                         uint32_t b0, uint32_t b1) {
    asm volatile(
        "mma.sync.aligned.m16n8k16.row.col.f32.f16.f16.f32 "
        "{%0,%1,%2,%3}, {%4,%5,%6,%7}, {%8,%9}, {%0,%1,%2,%3};"
        : "+f"(c[0]), "+f"(c[1]), "+f"(c[2]), "+f"(c[3])
        : "r"(a0), "r"(a1), "r"(a2), "r"(a3), "r"(b0), "r"(b1));
}

#define ASTR 200
#define EL_AH 0
#define EL_AL 12800
#define EL_BH 25600
#define EL_BL 38400
#define DSM_BYTES (51200 * 2)

__global__ void __launch_bounds__(256) k_gemm_mma(
    const float* __restrict__ Hm, const float* __restrict__ Bb,
    float* __restrict__ OUT, int whichsel)
{
    extern __shared__ unsigned short sm_el[];
    unsigned short* Ah = sm_el + EL_AH;
    unsigned short* Al = sm_el + EL_AL;
    unsigned short* Bh = sm_el + EL_BH;
    unsigned short* Bl = sm_el + EL_BL;

    int tid = threadIdx.x;
    int wid = tid >> 5, lane = tid & 31;
    int rowbase = blockIdx.x * 64;
    int which = (whichsel == 2) ? 2 : (int)blockIdx.y;

    const uint32_t *hsrc[3], *lsrc[3];
    int st, off;
    float* Cbase; int gates, wstart, wstep;
    if (which == 0) {
        hsrc[0] = (const uint32_t*)g_XHt; lsrc[0] = (const uint32_t*)g_XHlo;
        hsrc[1] = (const uint32_t*)g_T1t; lsrc[1] = (const uint32_t*)g_T1lo;
        hsrc[2] = (const uint32_t*)g_T2t; lsrc[2] = (const uint32_t*)g_T2lo;
        st = 2; off = 0; Cbase = g_GA; gates = 3; wstart = 0; wstep = 2;
    } else if (which == 1) {
        hsrc[0] = (const uint32_t*)g_XHt; lsrc[0] = (const uint32_t*)g_XHlo;
        hsrc[1] = (const uint32_t*)g_T1t; lsrc[1] = (const uint32_t*)g_T1lo;
        hsrc[2] = (const uint32_t*)g_T2t; lsrc[2] = (const uint32_t*)g_T2lo;
        st = 2; off = 1; Cbase = g_GB; gates = 2; wstart = 1; wstep = 2;
    } else {
        hsrc[0] = g_HRt;   lsrc[0] = g_HRlo;
        hsrc[1] = g_THR1t; lsrc[1] = g_THR1lo;
        hsrc[2] = g_THR2t; lsrc[2] = g_THR2lo;
        st = 1; off = 0; Cbase = 0; gates = 1; wstart = 5; wstep = 0;
    }

    // ---- stage A: copy hi/lo words from unified tables ----
    uint32_t* Ahw = (uint32_t*)Ah;
    uint32_t* Alw = (uint32_t*)Al;
    #pragma unroll
    for (int c = 0; c < 3; c++) {
        const uint32_t* sh = hsrc[c];
        const uint32_t* sl = lsrc[c];
        #pragma unroll
        for (int i = 0; i < 8; i++) {
            int lin = tid + i * 256;          // 2048 words: (m, k)
            int m = lin >> 5;
            int k = lin & 31;
            int grow = rowbase + m;
            uint32_t vh = 0, vl = 0;
            if (grow < NN) {
                int idx = (grow * 32 + k) * st + off;
                vh = sh[idx];
                vl = sl[idx];
            }
            int wo = m * 100 + c * 32 + k;    // word offset (ASTR/2 = 100)
            Ahw[wo] = vh;
            Alw[wo] = vl;
        }
    }
    __syncthreads();

    int gq = lane >> 2, tg = lane & 3;
    int rw = wid & 3, nh = wid >> 2;
    int mrow = rw * 16;
    const uint32_t* pAh = (const uint32_t*)(Ah + (mrow + gq) * ASTR + tg * 2);
    const uint32_t* pAl = (const uint32_t*)(Al + (mrow + gq) * ASTR + tg * 2);
    const uint32_t* pBh0 = (const uint32_t*)(Bh + gq * ASTR + tg * 2) + nh * 3200;
    const uint32_t* pBl0 = (const uint32_t*)(Bl + gq * ASTR + tg * 2) + nh * 3200;

    for (int g = 0; g < gates; g++) {
        int wsel = wstart + g * wstep;
        #pragma unroll
        for (int c = 0; c < 3; c++) {
            int mat = wsel * 3 + c;
            const uint4* srcH = (const uint4*)(g_Wh + (mat << 12));
            const uint4* srcL = (const uint4*)(g_Wl + (mat << 12));
            #pragma unroll
            for (int i = 0; i < 2; i++) {
                int lin = tid + i * 256;
                int d  = lin >> 3;
                int k8 = (lin & 7) * 8;
                int eo = d * ASTR + c * 64 + k8;
                *(uint4*)(Bh + eo) = srcH[lin];
                *(uint4*)(Bl + eo) = srcL[lin];
            }
        }
        __syncthreads();

        float acc[16];
        #pragma unroll
        for (int i = 0; i < 16; i++) acc[i] = 0.f;

        #pragma unroll 2
        for (int ks = 0; ks < 12; ks++) {
            int kw = ks * 8;
            uint32_t ah0 = pAh[kw], ah1 = pAh[kw + 800];
            uint32_t ah2 = pAh[kw + 4], ah3 = pAh[kw + 804];
            uint32_t al0 = pAl[kw], al1 = pAl[kw + 800];
            uint32_t al2 = pAl[kw + 4], al3 = pAl[kw + 804];
            #pragma unroll
            for (int nt = 0; nt < 4; nt++) {
                int bo = nt * 800 + kw;
                uint32_t bh0 = pBh0[bo], bh1 = pBh0[bo + 4];
                uint32_t bl0 = pBl0[bo], bl1 = pBl0[bo + 4];
                float* a = acc + nt * 4;
                mma16816(a, ah0, ah1, ah2, ah3, bh0, bh1);
                mma16816(a, ah0, ah1, ah2, ah3, bl0, bl1);
                mma16816(a, al0, al1, al2, al3, bh0, bh1);
            }
        }

        int r0 = rowbase + mrow + gq;
        int r1 = r0 + 8;
        if (whichsel != 2) {
            float* C = Cbase + (size_t)g * NND;
            #pragma unroll
            for (int nt = 0; nt < 4; nt++) {
                int col = (nh * 4 + nt) * 8 + tg * 2;
                if (r0 < NN) *(float2*)(C + (size_t)r0 * DD + col) = make_float2(acc[nt*4+0], acc[nt*4+1]);
                if (r1 < NN) *(float2*)(C + (size_t)r1 * DD + col) = make_float2(acc[nt*4+2], acc[nt*4+3]);
            }
        } else {
            #pragma unroll
            for (int nt = 0; nt < 4; nt++) {
                int col = (nh * 4 + nt) * 8 + tg * 2;
                float bs0 = __ldg(Bb + 256 + col)     + __ldg(Bb + 320 + col);
                float bs1 = __ldg(Bb + 256 + col + 1) + __ldg(Bb + 320 + col + 1);
                if (r0 < NN) {
                    size_t o = (size_t)r0 * DD + col;
                    float2 gx = *(const float2*)(g_GA + 2u * NND + o);
                    float2 z  = *(const float2*)(g_Z + o);
                    float2 h  = *(const float2*)(Hm + o);
                    float2 ov;
                    ov.x = z.x * tanhf(gx.x + acc[nt*4+0] + bs0) + (1.f - z.x) * h.x;
                    ov.y = z.y * tanhf(gx.y + acc[nt*4+1] + bs1) + (1.f - z.y) * h.y;
                    *(float2*)(OUT + o) = ov;
                }
                if (r1 < NN) {
                    size_t o = (size_t)r1 * DD + col;
                    float2 gx = *(const float2*)(g_GA + 2u * NND + o);
                    float2 z  = *(const float2*)(g_Z + o);
                    float2 h  = *(const float2*)(Hm + o);
                    float2 ov;
                    ov.x = z.x * tanhf(gx.x + acc[nt*4+2] + bs0) + (1.f - z.x) * h.x;
                    ov.y = z.y * tanhf(gx.y + acc[nt*4+3] + bs1) + (1.f - z.y) * h.y;
                    *(float2*)(OUT + o) = ov;
                }
            }
        }
        if (g + 1 < gates) __syncthreads();
    }
}

// ---------------- elementwise: Z, R, HR tables + next-replay reset ----------

__global__ void k_ew1(const float* __restrict__ Hm, const float* __restrict__ Bb) {
    int i4 = blockIdx.x * blockDim.x + threadIdx.x;
    if (i4 >= NND / 4) return;
    if (i4 < NN) { g_deg[i4] = 0.f; g_cnt[i4] = 0; }   // reset for next replay
    int i = i4 * 4;
    int d = i & (DD - 1);
    float4 ga0 = *(const float4*)(g_GA + i);
    float4 gb0 = *(const float4*)(g_GB + i);
    float4 ga1 = *(const float4*)(g_GA + (size_t)NND + i);
    float4 gb1 = *(const float4*)(g_GB + (size_t)NND + i);
    float4 b0  = *(const float4*)(Bb + d);
    float4 b1  = *(const float4*)(Bb + 64 + d);
    float4 b2  = *(const float4*)(Bb + 128 + d);
    float4 b3  = *(const float4*)(Bb + 192 + d);
    float4 h   = *(const float4*)(Hm + i);
    float4 z, hr;
    z.x = 1.f / (1.f + __expf(-(ga0.x + gb0.x + b0.x + b1.x)));
    z.y = 1.f / (1.f + __expf(-(ga0.y + gb0.y + b0.y + b1.y)));
    z.z = 1.f / (1.f + __expf(-(ga0.z + gb0.z + b0.z + b1.z)));
    z.w = 1.f / (1.f + __expf(-(ga0.w + gb0.w + b0.w + b1.w)));
    hr.x = h.x / (1.f + __expf(-(ga1.x + gb1.x + b2.x + b3.x)));
    hr.y = h.y / (1.f + __expf(-(ga1.y + gb1.y + b2.y + b3.y)));
    hr.z = h.z / (1.f + __expf(-(ga1.z + gb1.z + b2.z + b3.z)));
    hr.w = h.w / (1.f + __expf(-(ga1.w + gb1.w + b2.w + b3.w)));
    *(float4*)(g_Z + i) = z;
    uint32_t h0, l0, h1, l1;
    fsplitpack(make_float2(hr.x, hr.y), h0, l0);
    fsplitpack(make_float2(hr.z, hr.w), h1, l1);
    *(uint2*)(g_HRt + i4 * 2)  = make_uint2(h0, h1);
    *(uint2*)(g_HRlo + i4 * 2) = make_uint2(l0, l1);
}

// ---------------- launch ----------------------------------------------------

extern "C" void kernel_launch(void* const* d_in, const int* in_sizes, int n_in,
                              void* d_out, int out_size) {
    const float* X   = (const float*)d_in[0];
    const void*  EI  = d_in[1];
    const float* EW  = (const float*)d_in[2];
    const float* H   = (const float*)d_in[3];
    const float* LAM = (const float*)d_in[4];
    const float* W   = (const float*)d_in[5];
    const float* B   = (const float*)d_in[6];
    float* OUT = (float*)d_out;

    (void)in_sizes; (void)n_in; (void)out_size;

    cudaFuncSetAttribute(k_gemm_mma, cudaFuncAttributeMaxDynamicSharedMemorySize, DSM_BYTES);

    k_edge_deg<<<(EE + 255) / 256, 256>>>(EI, EW);                   // 0
    k_scan<<<1, 1024>>>();                                           // 1
    k_fillsetup<<<(NH + 255) / 256, 256>>>(EI, EW, X, H, W);         // 2

    dim3 sg((NN + 7) / 8);
    k_spmm1_XH<<<sg, 256>>>(LAM);                                    // 3 (profiled)
    k_spmm2_XH<<<sg, 256>>>(LAM);                                    // 4

    int ntiles = (NN + 63) / 64;
    k_gemm_mma<<<dim3(ntiles, 2), 256, DSM_BYTES>>>(H, B, OUT, 0);   // 5

    k_ew1<<<(NND / 4 + 255) / 256, 256>>>(H, B);                     // 6

    k_spmm1_HR<<<sg, 256>>>(LAM);                                    // 7
    k_spmm2_HR<<<sg, 256>>>(LAM);                                    // 8
    k_gemm_mma<<<dim3(ntiles, 1), 256, DSM_BYTES>>>(H, B, OUT, 2);   // 9
}